// round 13
// baseline (speedup 1.0000x reference)
#include <cuda_runtime.h>
#include <cstdint>

#define NNODES 50000
#define NEDGES 800000
#define TOTEDGES (NEDGES + NNODES)
#define NEG_SLOPE 0.2f

// ---------------- scratch (allocation-free: device globals) ----------------
__device__ float g_h0[(size_t)NNODES * 128];
__device__ float g_h0b[(size_t)NNODES * 128];
__device__ float g_h1[(size_t)NNODES * 128];
__device__ float g_s[NNODES * 2];
__device__ float g_t[NNODES * 2];
__device__ float g_sb[NNODES * 2];
__device__ float g_tb[NNODES * 2];
__device__ int   g_deg[NNODES];
__device__ int   g_rowptr[NNODES + 1];
__device__ int   g_cursor[NNODES];
__device__ int   g_col[TOTEDGES];
__device__ int   g_bsum[256];
__device__ int   g_bexc[256];
__device__ float g_Wcat[64 * 128];
__device__ float g_bcat[128];

// ---------------- helpers ----------------
__device__ __forceinline__ uint32_t smem_u32(const void* p) {
    return (uint32_t)__cvta_generic_to_shared(p);
}
typedef unsigned long long ull;
union F4U { float4 f; ull u[2]; };
__device__ __forceinline__ ull splat2(float x) {
    ull r;
    asm("mov.b64 %0, {%1, %1};" : "=l"(r) : "f"(x));
    return r;
}
__device__ __forceinline__ void fma2(ull& d, ull a, ull b) {
    asm("fma.rn.f32x2 %0, %1, %2, %3;" : "=l"(d) : "l"(a), "l"(b), "l"(d));
}
__device__ __forceinline__ void upk2(ull v, float& lo, float& hi) {
    asm("mov.b64 {%0, %1}, %2;" : "=f"(lo), "=f"(hi) : "l"(v));
}
__device__ __forceinline__ void cpa16(uint32_t dst, const void* src) {
    asm volatile("cp.async.cg.shared.global [%0], [%1], 16;" :: "r"(dst), "l"(src));
}

// ---------------- CSR build ----------------
__global__ void k_init_deg(int* __restrict__ deg, int n) {
    int i = blockIdx.x * blockDim.x + threadIdx.x;
    if (i < n) deg[i] = 1;
}
__global__ void k_hist(const int* __restrict__ ei, int e, int* __restrict__ deg) {
    int i = blockIdx.x * blockDim.x + threadIdx.x;
    if (i < e) atomicAdd(&deg[ei[e + i]], 1);
}
__global__ void k_blocksums(const int* __restrict__ deg, int* __restrict__ bsum, int n) {
    __shared__ int wred[8];
    int i = blockIdx.x * 256 + threadIdx.x;
    int v = (i < n) ? deg[i] : 0;
    int lane = threadIdx.x & 31, w = threadIdx.x >> 5;
#pragma unroll
    for (int off = 16; off; off >>= 1) v += __shfl_xor_sync(0xFFFFFFFFu, v, off);
    if (lane == 0) wred[w] = v;
    __syncthreads();
    if (threadIdx.x == 0) {
        int s = 0;
#pragma unroll
        for (int k = 0; k < 8; k++) s += wred[k];
        bsum[blockIdx.x] = s;
    }
}
__global__ void k_scan_top(const int* __restrict__ bsum, int* __restrict__ bexc, int nb) {
    __shared__ int wred[8];
    int tid = threadIdx.x, lane = tid & 31, w = tid >> 5;
    int v = (tid < nb) ? bsum[tid] : 0;
    int x = v;
#pragma unroll
    for (int off = 1; off < 32; off <<= 1) {
        int y = __shfl_up_sync(0xFFFFFFFFu, x, off);
        if (lane >= off) x += y;
    }
    if (lane == 31) wred[w] = x;
    __syncthreads();
    if (w == 0) {
        int sv = (lane < 8) ? wred[lane] : 0;
#pragma unroll
        for (int off = 1; off < 8; off <<= 1) {
            int y = __shfl_up_sync(0xFFFFFFFFu, sv, off);
            if (lane >= off) sv += y;
        }
        if (lane < 8) wred[lane] = sv;
    }
    __syncthreads();
    int woff = (w > 0) ? wred[w - 1] : 0;
    if (tid < nb) bexc[tid] = x + woff - v;
}
__global__ void k_scan_apply(const int* __restrict__ deg, const int* __restrict__ bexc,
                             int* __restrict__ rowptr, int* __restrict__ cursor,
                             int* __restrict__ col, int n) {
    __shared__ int wred[8];
    int i = blockIdx.x * 256 + threadIdx.x;
    int tid = threadIdx.x, lane = tid & 31, w = tid >> 5;
    int v = (i < n) ? deg[i] : 0;
    int x = v;
#pragma unroll
    for (int off = 1; off < 32; off <<= 1) {
        int y = __shfl_up_sync(0xFFFFFFFFu, x, off);
        if (lane >= off) x += y;
    }
    if (lane == 31) wred[w] = x;
    __syncthreads();
    if (w == 0) {
        int sv = (lane < 8) ? wred[lane] : 0;
#pragma unroll
        for (int off = 1; off < 8; off <<= 1) {
            int y = __shfl_up_sync(0xFFFFFFFFu, sv, off);
            if (lane >= off) sv += y;
        }
        if (lane < 8) wred[lane] = sv;
    }
    __syncthreads();
    int woff = (w > 0) ? wred[w - 1] : 0;
    if (i < n) {
        int incl = x + woff + bexc[blockIdx.x];
        rowptr[i + 1] = incl;
        int p = incl - v;
        col[p] = i;
        cursor[i] = p + 1;
        if (i == 0) rowptr[0] = 0;
    }
}
__global__ void k_scatter(const int* __restrict__ ei, int e, int* __restrict__ cursor,
                          int* __restrict__ col) {
    int i = blockIdx.x * blockDim.x + threadIdx.x;
    if (i < e) {
        int s = ei[i];
        int d = ei[e + i];
        int p = atomicAdd(&cursor[d], 1);
        col[p] = s;
    }
}

// ---------------- Wcat prep ----------------
__global__ void k_prep(const float* __restrict__ Wv, const float* __restrict__ bv,
                       const float* __restrict__ Wt, const float* __restrict__ bt,
                       float* __restrict__ Wcat, float* __restrict__ bcat) {
    int i = blockIdx.x * blockDim.x + threadIdx.x;
    if (i < 64 * 128) {
        int k = i >> 7, n = i & 127;
        Wcat[i] = (n < 64) ? Wv[k * 64 + n] : Wt[k * 64 + (n - 64)];
    }
    if (i < 128) bcat[i] = (i < 64) ? bv[i] : bt[i - 64];
}

// ---------------- f32x2 GEMM (R8/R10 proven shape), with lda for split-K ------
template <int BN>
__global__ void __launch_bounds__(256, 2) k_gemm(
    const float* __restrict__ A, int lda, const float* __restrict__ B,
    float* __restrict__ C, float* __restrict__ C2, int M, int K,
    const float* __restrict__ bias, int relu,
    const float* __restrict__ a_src, const float* __restrict__ a_dst,
    float* __restrict__ s_out, float* __restrict__ t_out)
{
    constexpr int BM = 128, BK = 16, TN = BN / 16;
    constexpr int NG = BN / 64;
    __shared__ float As[2][BM][BK];
    __shared__ float Bs[2][BK][BN];
    __shared__ float sh_att[2 * BN];

    int tid = threadIdx.x;
    int tx = tid & 15, ty = tid >> 4;
    int blockRow = blockIdx.x * BM;

    if (a_src) {
        if (tid < BN) sh_att[tid] = a_src[tid];
        else if (tid < 2 * BN) sh_att[tid] = a_dst[tid - BN];
    }

    ull acc[8][TN / 2];
#pragma unroll
    for (int i = 0; i < 8; i++)
#pragma unroll
        for (int j = 0; j < TN / 2; j++) acc[i][j] = 0ull;

    int nch = K / BK;

    auto loadA = [&](int c, int st) {
        int k0 = c * BK;
#pragma unroll
        for (int l = 0; l < 2; l++) {
            int f = tid + l * 256;
            int row = f >> 2, q = f & 3;
            int gr = blockRow + row;
            if (gr >= M) gr = M - 1;
            cpa16(smem_u32(&As[st][row][q * 4]), &A[(size_t)gr * lda + k0 + q * 4]);
        }
    };
    auto loadB = [&](int c, int st) {
        int k0 = c * BK;
        constexpr int CH = BK * BN / 4;
#pragma unroll
        for (int l = 0; l < CH / 256; l++) {
            int f = tid + l * 256;
            int kr = f / (BN / 4), q = f % (BN / 4);
            cpa16(smem_u32(&Bs[st][kr][q * 4]), &B[(size_t)(k0 + kr) * BN + q * 4]);
        }
    };

    loadA(0, 0);
    loadB(0, 0);
    asm volatile("cp.async.commit_group;");

    for (int c = 0; c < nch; c++) {
        int st = c & 1;
        if (c + 1 < nch) {
            loadA(c + 1, (c + 1) & 1);
            loadB(c + 1, (c + 1) & 1);
            asm volatile("cp.async.commit_group;");
            asm volatile("cp.async.wait_group 1;");
        } else {
            asm volatile("cp.async.wait_group 0;");
        }
        __syncthreads();

#pragma unroll
        for (int k4 = 0; k4 < BK; k4 += 4) {
            float4 a4[8];
#pragma unroll
            for (int i = 0; i < 8; i++)
                a4[i] = *reinterpret_cast<const float4*>(&As[st][ty * 8 + i][k4]);
#pragma unroll
            for (int kk = 0; kk < 4; kk++) {
                ull b2[TN / 2];
#pragma unroll
                for (int g = 0; g < NG; g++) {
                    F4U bu;
                    bu.f = *reinterpret_cast<const float4*>(&Bs[st][k4 + kk][g * 64 + tx * 4]);
                    b2[g * 2 + 0] = bu.u[0];
                    b2[g * 2 + 1] = bu.u[1];
                }
#pragma unroll
                for (int i = 0; i < 8; i++) {
                    float av = (kk == 0) ? a4[i].x : (kk == 1) ? a4[i].y : (kk == 2) ? a4[i].z : a4[i].w;
                    ull a2 = splat2(av);
#pragma unroll
                    for (int j = 0; j < TN / 2; j++) fma2(acc[i][j], a2, b2[j]);
                }
            }
        }
        __syncthreads();
    }

    // ---- per-row epilogue ----
#pragma unroll
    for (int i = 0; i < 8; i++) {
        int r = blockRow + ty * 8 + i;
        float af[TN];
#pragma unroll
        for (int j = 0; j < TN / 2; j++) upk2(acc[i][j], af[2 * j], af[2 * j + 1]);

        if (s_out) {
            if (BN == 128) {
                float ps0 = 0.f, pt0 = 0.f, ps1 = 0.f, pt1 = 0.f;
#pragma unroll
                for (int j = 0; j < 4; j++) {
                    int c0 = tx * 4 + j, c1 = 64 + tx * 4 + j;
                    ps0 += af[j] * sh_att[c0];
                    pt0 += af[j] * sh_att[BN + c0];
                    ps1 += af[4 + j] * sh_att[c1];
                    pt1 += af[4 + j] * sh_att[BN + c1];
                }
#pragma unroll
                for (int off = 8; off; off >>= 1) {
                    ps0 += __shfl_xor_sync(0xFFFFFFFFu, ps0, off);
                    pt0 += __shfl_xor_sync(0xFFFFFFFFu, pt0, off);
                    ps1 += __shfl_xor_sync(0xFFFFFFFFu, ps1, off);
                    pt1 += __shfl_xor_sync(0xFFFFFFFFu, pt1, off);
                }
                if (tx == 0 && r < M) {
                    s_out[r * 2 + 0] = ps0;
                    s_out[r * 2 + 1] = ps1;
                    t_out[r * 2 + 0] = pt0;
                    t_out[r * 2 + 1] = pt1;
                }
            } else {
                float ps = 0.f, pt = 0.f;
#pragma unroll
                for (int j = 0; j < 4; j++) {
                    int col = tx * 4 + j;
                    ps += af[j] * sh_att[col];
                    pt += af[j] * sh_att[BN + col];
                }
#pragma unroll
                for (int off = 8; off; off >>= 1) {
                    ps += __shfl_xor_sync(0xFFFFFFFFu, ps, off);
                    pt += __shfl_xor_sync(0xFFFFFFFFu, pt, off);
                }
                if (tx == 0 && r < M) {
                    s_out[r] = ps;
                    t_out[r] = pt;
                }
            }
        }

        if (r < M) {
#pragma unroll
            for (int g = 0; g < NG; g++) {
                int col = g * 64 + tx * 4;
                float4 v;
                v.x = af[g * 4 + 0];
                v.y = af[g * 4 + 1];
                v.z = af[g * 4 + 2];
                v.w = af[g * 4 + 3];
                if (bias) {
                    v.x += bias[col + 0]; v.y += bias[col + 1];
                    v.z += bias[col + 2]; v.w += bias[col + 3];
                }
                if (relu) {
                    v.x = fmaxf(v.x, 0.f); v.y = fmaxf(v.y, 0.f);
                    v.z = fmaxf(v.z, 0.f); v.w = fmaxf(v.w, 0.f);
                }
                if (C2) {
                    float* dst = (g == 0) ? C : C2;
                    *reinterpret_cast<float4*>(&dst[(size_t)r * 64 + tx * 4]) = v;
                } else {
                    *reinterpret_cast<float4*>(&C[(size_t)r * BN + col]) = v;
                }
            }
        }
    }
}

// ---------------- GAT aggregation: one WARP per dst node ----------------
// DUAL: inputs are (hin+hin2, s+s2, t+t2) elementwise sums (split-K partials).
template <int H, bool RELU, bool DUAL>
__global__ void __launch_bounds__(256) k_aggw(const float* __restrict__ hin,
                                              const float* __restrict__ hin2,
                                              const float* __restrict__ s,
                                              const float* __restrict__ s2p,
                                              const float* __restrict__ t,
                                              const float* __restrict__ t2p,
                                              const int* __restrict__ rowptr,
                                              const int* __restrict__ col,
                                              const float* __restrict__ bias,
                                              float* __restrict__ out, int n) {
    constexpr int W = H * 64;
    constexpr int C = W / 32;
    int node = (blockIdx.x * 256 + threadIdx.x) >> 5;
    if (node >= n) return;
    int lane = threadIdx.x & 31;
    int start = rowptr[node];
    int deg = rowptr[node + 1] - start;

    float tn[H];
#pragma unroll
    for (int h = 0; h < H; h++) {
        tn[h] = t[node * H + h];
        if (DUAL) tn[h] += t2p[node * H + h];
    }

    float acc[C];
#pragma unroll
    for (int c = 0; c < C; c++) acc[c] = 0.f;

    auto load_s = [&](int src, float& e0, float& e1) {
        if (H == 2) {
            float2 sv = *reinterpret_cast<const float2*>(&s[src * 2]);
            float sx = sv.x, sy = sv.y;
            if (DUAL) {
                float2 sv2 = *reinterpret_cast<const float2*>(&s2p[src * 2]);
                sx += sv2.x; sy += sv2.y;
            }
            e0 = sx + tn[0];
            e0 = e0 > 0.f ? e0 : NEG_SLOPE * e0;
            e1 = sy + tn[1];
            e1 = e1 > 0.f ? e1 : NEG_SLOPE * e1;
        } else {
            float sx = s[src];
            if (DUAL) sx += s2p[src];
            e0 = sx + tn[0];
            e0 = e0 > 0.f ? e0 : NEG_SLOPE * e0;
            e1 = e0;
        }
    };

    if (deg <= 32) {
        int src = 0;
        float e0 = -1e30f, e1 = -1e30f;
        bool act = lane < deg;
        if (act) {
            src = col[start + lane];
            load_s(src, e0, e1);
        }
        float m0 = e0, m1 = e1;
#pragma unroll
        for (int off = 16; off; off >>= 1) {
            m0 = fmaxf(m0, __shfl_xor_sync(0xFFFFFFFFu, m0, off));
            if (H == 2) m1 = fmaxf(m1, __shfl_xor_sync(0xFFFFFFFFu, m1, off));
        }
        float x0 = act ? __expf(e0 - m0) : 0.f;
        float x1 = (H == 2 && act) ? __expf(e1 - m1) : 0.f;
        float s0 = x0, s1 = x1;
#pragma unroll
        for (int off = 16; off; off >>= 1) {
            s0 += __shfl_xor_sync(0xFFFFFFFFu, s0, off);
            if (H == 2) s1 += __shfl_xor_sync(0xFFFFFFFFu, s1, off);
        }
        float al0 = x0 / (s0 + 1e-16f);
        float al1 = (H == 2) ? x1 / (s1 + 1e-16f) : al0;

        for (int e2 = 0; e2 < deg; e2++) {
            int sb = __shfl_sync(0xFFFFFFFFu, src, e2);
            float a0 = __shfl_sync(0xFFFFFFFFu, al0, e2);
            float a1 = (H == 2) ? __shfl_sync(0xFFFFFFFFu, al1, e2) : a0;
            const float* hp = hin + (size_t)sb * W;
            const float* hp2 = DUAL ? hin2 + (size_t)sb * W : nullptr;
#pragma unroll
            for (int c = 0; c < C; c++) {
                float a = (H == 2) ? ((c < 2) ? a0 : a1) : a0;
                float hv = hp[lane + 32 * c];
                if (DUAL) hv += hp2[lane + 32 * c];
                acc[c] = fmaf(a, hv, acc[c]);
            }
        }
    } else {
        float m[H], sm[H];
#pragma unroll
        for (int h = 0; h < H; h++) { m[h] = -1e30f; sm[h] = 0.f; }
        for (int k = lane; k < deg; k += 32) {
            int src = col[start + k];
            float e[2];
            load_s(src, e[0], e[1]);
#pragma unroll
            for (int h = 0; h < H; h++) {
                float eh = e[h];
                float old = m[h];
                float nm = fmaxf(old, eh);
                sm[h] = sm[h] * __expf(old - nm) + __expf(eh - nm);
                m[h] = nm;
            }
        }
        float inv[H];
#pragma unroll
        for (int h = 0; h < H; h++) {
#pragma unroll
            for (int off = 16; off; off >>= 1) {
                float mo = __shfl_xor_sync(0xFFFFFFFFu, m[h], off);
                float so = __shfl_xor_sync(0xFFFFFFFFu, sm[h], off);
                float nm = fmaxf(m[h], mo);
                sm[h] = sm[h] * __expf(m[h] - nm) + so * __expf(mo - nm);
                m[h] = nm;
            }
            inv[h] = 1.f / (sm[h] + 1e-16f);
        }

        for (int base = 0; base < deg; base += 32) {
            int k = base + lane;
            int src = 0;
            float al0 = 0.f, al1 = 0.f;
            if (k < deg) {
                src = col[start + k];
                float e0, e1;
                load_s(src, e0, e1);
                al0 = __expf(e0 - m[0]) * inv[0];
                if (H == 2) al1 = __expf(e1 - m[1]) * inv[1];
            }
            int nk = min(32, deg - base);
            for (int e2 = 0; e2 < nk; e2++) {
                int sb = __shfl_sync(0xFFFFFFFFu, src, e2);
                float a0 = __shfl_sync(0xFFFFFFFFu, al0, e2);
                float a1 = (H == 2) ? __shfl_sync(0xFFFFFFFFu, al1, e2) : a0;
                const float* hp = hin + (size_t)sb * W;
                const float* hp2 = DUAL ? hin2 + (size_t)sb * W : nullptr;
#pragma unroll
                for (int c = 0; c < C; c++) {
                    float a = (H == 2) ? ((c < 2) ? a0 : a1) : a0;
                    float hv = hp[lane + 32 * c];
                    if (DUAL) hv += hp2[lane + 32 * c];
                    acc[c] = fmaf(a, hv, acc[c]);
                }
            }
        }
    }

#pragma unroll
    for (int c = 0; c < C; c++) {
        float v = acc[c] + bias[lane + 32 * c];
        if (RELU) v = fmaxf(v, 0.f);
        out[(size_t)node * W + lane + 32 * c] = v;
    }
}

// ---------------- host launch ----------------
extern "C" void kernel_launch(void* const* d_in, const int* in_sizes, int n_in,
                              void* d_out, int out_size) {
    const float* x     = (const float*)d_in[0];
    const int*   ei    = (const int*)d_in[1];
    const float* W0    = (const float*)d_in[2];
    const float* as0   = (const float*)d_in[3];
    const float* ad0   = (const float*)d_in[4];
    const float* b0    = (const float*)d_in[5];
    const float* W1    = (const float*)d_in[6];
    const float* as1   = (const float*)d_in[7];
    const float* ad1   = (const float*)d_in[8];
    const float* b1    = (const float*)d_in[9];
    const float* W2    = (const float*)d_in[10];
    const float* as2   = (const float*)d_in[11];
    const float* ad2   = (const float*)d_in[12];
    const float* b2    = (const float*)d_in[13];
    const float* Wv    = (const float*)d_in[14];
    const float* bv    = (const float*)d_in[15];
    const float* Wt    = (const float*)d_in[16];
    const float* bt    = (const float*)d_in[17];

    int N = in_sizes[0] / 512;
    int E = in_sizes[1] / 2;

    float* out = (float*)d_out;
    float* h_out = out;
    float* vis = out + (size_t)N * 64;
    float* txt = out + (size_t)N * 64 * 2;

    float *h0, *h0b, *h1, *sA, *tA, *sB, *tB, *Wcat, *bcat;
    int *deg, *rowptr, *cursor, *colA, *bsum, *bexc;
    cudaGetSymbolAddress((void**)&h0, g_h0);
    cudaGetSymbolAddress((void**)&h0b, g_h0b);
    cudaGetSymbolAddress((void**)&h1, g_h1);
    cudaGetSymbolAddress((void**)&sA, g_s);
    cudaGetSymbolAddress((void**)&tA, g_t);
    cudaGetSymbolAddress((void**)&sB, g_sb);
    cudaGetSymbolAddress((void**)&tB, g_tb);
    cudaGetSymbolAddress((void**)&deg, g_deg);
    cudaGetSymbolAddress((void**)&rowptr, g_rowptr);
    cudaGetSymbolAddress((void**)&cursor, g_cursor);
    cudaGetSymbolAddress((void**)&colA, g_col);
    cudaGetSymbolAddress((void**)&bsum, g_bsum);
    cudaGetSymbolAddress((void**)&bexc, g_bexc);
    cudaGetSymbolAddress((void**)&Wcat, g_Wcat);
    cudaGetSymbolAddress((void**)&bcat, g_bcat);

    static cudaStream_t s2 = nullptr, s3 = nullptr;
    static cudaEvent_t ev[5];
    if (!s2) {
        cudaStreamCreateWithFlags(&s2, cudaStreamNonBlocking);
        cudaStreamCreateWithFlags(&s3, cudaStreamNonBlocking);
        for (int i = 0; i < 5; i++) cudaEventCreateWithFlags(&ev[i], cudaEventDisableTiming);
    }

    int nb = (N + 255) / 256;
    int gblk = (N + 127) / 128;
    int wgrid = (N * 32 + 255) / 256;

    // ---- fork: CSR + Wcat prep on s2, GEMM0 half-B on s3, half-A on main ----
    cudaEventRecord(ev[0], 0);
    cudaStreamWaitEvent(s2, ev[0], 0);
    cudaStreamWaitEvent(s3, ev[0], 0);

    k_init_deg<<<nb, 256, 0, s2>>>(deg, N);
    k_hist<<<(E + 255) / 256, 256, 0, s2>>>(ei, E, deg);
    k_blocksums<<<nb, 256, 0, s2>>>(deg, bsum, N);
    k_scan_top<<<1, 256, 0, s2>>>(bsum, bexc, nb);
    k_scan_apply<<<nb, 256, 0, s2>>>(deg, bexc, rowptr, cursor, colA, N);
    k_scatter<<<(E + 255) / 256, 256, 0, s2>>>(ei, E, cursor, colA);
    k_prep<<<(64 * 128 + 255) / 256, 256, 0, s2>>>(Wv, bv, Wt, bt, Wcat, bcat);
    cudaEventRecord(ev[1], s2);

    // GEMM0 split-K: half B = K[256:512) on s3
    k_gemm<128><<<gblk, 256, 0, s3>>>(x + 256, 512, W0 + 256 * 128, h0b, nullptr,
                                      N, 256, nullptr, 0, as0, ad0, sB, tB);
    cudaEventRecord(ev[2], s3);

    // half A = K[0:256) on main stream
    k_gemm<128><<<gblk, 256>>>(x, 512, W0, h0, nullptr,
                               N, 256, nullptr, 0, as0, ad0, sA, tA);
    cudaStreamWaitEvent(0, ev[1], 0);
    cudaStreamWaitEvent(0, ev[2], 0);

    // ---- layer 0 aggregation (DUAL: sums the two split-K partials) ----
    k_aggw<2, true, true><<<wgrid, 256>>>(h0, h0b, sA, sB, tA, tB,
                                          rowptr, colA, b0, h1, N);

    // ---- layer 1 ----
    k_gemm<128><<<gblk, 256>>>(h1, 128, W1, h0, nullptr, N, 128, nullptr, 0,
                               as1, ad1, sA, tA);
    k_aggw<2, true, false><<<wgrid, 256>>>(h0, nullptr, sA, nullptr, tA, nullptr,
                                           rowptr, colA, b1, h1, N);

    // ---- layer 2 (heads=1, no relu) ----
    k_gemm<64><<<gblk, 256>>>(h1, 128, W2, h0, nullptr, N, 128, nullptr, 0,
                              as2, ad2, sA, tA);
    k_aggw<1, false, false><<<wgrid, 256>>>(h0, nullptr, sA, nullptr, tA, nullptr,
                                            rowptr, colA, b2, h_out, N);

    // ---- MLP heads: one combined GEMM with split store ----
    k_gemm<128><<<gblk, 256>>>(h_out, 64, Wcat, vis, txt, N, 64, bcat, 1,
                               nullptr, nullptr, nullptr, nullptr);
}

// round 14
// speedup vs baseline: 1.0991x; 1.0991x over previous
#include <cuda_runtime.h>
#include <cstdint>

#define NNODES 50000
#define NEDGES 800000
#define TOTEDGES (NEDGES + NNODES)
#define NEG_SLOPE 0.2f

// ---------------- scratch (allocation-free: device globals) ----------------
__device__ float g_h0[(size_t)NNODES * 128];
__device__ float g_h1[(size_t)NNODES * 128];
__device__ float g_s[NNODES * 2];
__device__ float g_t[NNODES * 2];
__device__ int   g_deg[NNODES];
__device__ int   g_rowptr[NNODES + 1];
__device__ int   g_cursor[NNODES];
__device__ int   g_col[TOTEDGES];
__device__ int   g_bsum[256];
__device__ int   g_bexc[256];
__device__ float g_Wcat[64 * 128];
__device__ float g_bcat[128];

// ---------------- helpers ----------------
__device__ __forceinline__ uint32_t smem_u32(const void* p) {
    return (uint32_t)__cvta_generic_to_shared(p);
}
typedef unsigned long long ull;
union F4U { float4 f; ull u[2]; };
__device__ __forceinline__ ull splat2(float x) {
    ull r;
    asm("mov.b64 %0, {%1, %1};" : "=l"(r) : "f"(x));
    return r;
}
__device__ __forceinline__ void fma2(ull& d, ull a, ull b) {
    asm("fma.rn.f32x2 %0, %1, %2, %3;" : "=l"(d) : "l"(a), "l"(b), "l"(d));
}
__device__ __forceinline__ void upk2(ull v, float& lo, float& hi) {
    asm("mov.b64 {%0, %1}, %2;" : "=f"(lo), "=f"(hi) : "l"(v));
}
__device__ __forceinline__ void cpa16(uint32_t dst, const void* src) {
    asm volatile("cp.async.cg.shared.global [%0], [%1], 16;" :: "r"(dst), "l"(src));
}

// ---------------- CSR build ----------------
__global__ void k_init_deg(int* __restrict__ deg, int n) {
    int i = blockIdx.x * blockDim.x + threadIdx.x;
    if (i < n) deg[i] = 1;
}
__global__ void k_hist(const int* __restrict__ ei, int e, int* __restrict__ deg) {
    int i = blockIdx.x * blockDim.x + threadIdx.x;
    if (i < e) atomicAdd(&deg[ei[e + i]], 1);
}
__global__ void k_blocksums(const int* __restrict__ deg, int* __restrict__ bsum, int n) {
    __shared__ int wred[8];
    int i = blockIdx.x * 256 + threadIdx.x;
    int v = (i < n) ? deg[i] : 0;
    int lane = threadIdx.x & 31, w = threadIdx.x >> 5;
#pragma unroll
    for (int off = 16; off; off >>= 1) v += __shfl_xor_sync(0xFFFFFFFFu, v, off);
    if (lane == 0) wred[w] = v;
    __syncthreads();
    if (threadIdx.x == 0) {
        int s = 0;
#pragma unroll
        for (int k = 0; k < 8; k++) s += wred[k];
        bsum[blockIdx.x] = s;
    }
}
__global__ void k_scan_top(const int* __restrict__ bsum, int* __restrict__ bexc, int nb) {
    __shared__ int wred[8];
    int tid = threadIdx.x, lane = tid & 31, w = tid >> 5;
    int v = (tid < nb) ? bsum[tid] : 0;
    int x = v;
#pragma unroll
    for (int off = 1; off < 32; off <<= 1) {
        int y = __shfl_up_sync(0xFFFFFFFFu, x, off);
        if (lane >= off) x += y;
    }
    if (lane == 31) wred[w] = x;
    __syncthreads();
    if (w == 0) {
        int sv = (lane < 8) ? wred[lane] : 0;
#pragma unroll
        for (int off = 1; off < 8; off <<= 1) {
            int y = __shfl_up_sync(0xFFFFFFFFu, sv, off);
            if (lane >= off) sv += y;
        }
        if (lane < 8) wred[lane] = sv;
    }
    __syncthreads();
    int woff = (w > 0) ? wred[w - 1] : 0;
    if (tid < nb) bexc[tid] = x + woff - v;
}
__global__ void k_scan_apply(const int* __restrict__ deg, const int* __restrict__ bexc,
                             int* __restrict__ rowptr, int* __restrict__ cursor,
                             int* __restrict__ col, int n) {
    __shared__ int wred[8];
    int i = blockIdx.x * 256 + threadIdx.x;
    int tid = threadIdx.x, lane = tid & 31, w = tid >> 5;
    int v = (i < n) ? deg[i] : 0;
    int x = v;
#pragma unroll
    for (int off = 1; off < 32; off <<= 1) {
        int y = __shfl_up_sync(0xFFFFFFFFu, x, off);
        if (lane >= off) x += y;
    }
    if (lane == 31) wred[w] = x;
    __syncthreads();
    if (w == 0) {
        int sv = (lane < 8) ? wred[lane] : 0;
#pragma unroll
        for (int off = 1; off < 8; off <<= 1) {
            int y = __shfl_up_sync(0xFFFFFFFFu, sv, off);
            if (lane >= off) sv += y;
        }
        if (lane < 8) wred[lane] = sv;
    }
    __syncthreads();
    int woff = (w > 0) ? wred[w - 1] : 0;
    if (i < n) {
        int incl = x + woff + bexc[blockIdx.x];
        rowptr[i + 1] = incl;
        int p = incl - v;
        col[p] = i;
        cursor[i] = p + 1;
        if (i == 0) rowptr[0] = 0;
    }
}
__global__ void k_scatter(const int* __restrict__ ei, int e, int* __restrict__ cursor,
                          int* __restrict__ col) {
    int i = blockIdx.x * blockDim.x + threadIdx.x;
    if (i < e) {
        int s = ei[i];
        int d = ei[e + i];
        int p = atomicAdd(&cursor[d], 1);
        col[p] = s;
    }
}

// ---------------- Wcat prep ----------------
__global__ void k_prep(const float* __restrict__ Wv, const float* __restrict__ bv,
                       const float* __restrict__ Wt, const float* __restrict__ bt,
                       float* __restrict__ Wcat, float* __restrict__ bcat) {
    int i = blockIdx.x * blockDim.x + threadIdx.x;
    if (i < 64 * 128) {
        int k = i >> 7, n = i & 127;
        Wcat[i] = (n < 64) ? Wv[k * 64 + n] : Wt[k * 64 + (n - 64)];
    }
    if (i < 128) bcat[i] = (i < 64) ? bv[i] : bt[i - 64];
}

// ---------------- f32x2 GEMM (R8/R10 proven shape) ----------------
template <int BN>
__global__ void __launch_bounds__(256, 2) k_gemm(
    const float* __restrict__ A, const float* __restrict__ B,
    float* __restrict__ C, float* __restrict__ C2, int M, int K,
    const float* __restrict__ bias, int relu,
    const float* __restrict__ a_src, const float* __restrict__ a_dst,
    float* __restrict__ s_out, float* __restrict__ t_out)
{
    constexpr int BM = 128, BK = 16, TN = BN / 16;
    constexpr int NG = BN / 64;
    __shared__ float As[2][BM][BK];
    __shared__ float Bs[2][BK][BN];
    __shared__ float sh_att[2 * BN];

    int tid = threadIdx.x;
    int tx = tid & 15, ty = tid >> 4;
    int blockRow = blockIdx.x * BM;

    if (a_src) {
        if (tid < BN) sh_att[tid] = a_src[tid];
        else if (tid < 2 * BN) sh_att[tid] = a_dst[tid - BN];
    }

    ull acc[8][TN / 2];
#pragma unroll
    for (int i = 0; i < 8; i++)
#pragma unroll
        for (int j = 0; j < TN / 2; j++) acc[i][j] = 0ull;

    int nch = K / BK;

    auto loadA = [&](int c, int st) {
        int k0 = c * BK;
#pragma unroll
        for (int l = 0; l < 2; l++) {
            int f = tid + l * 256;
            int row = f >> 2, q = f & 3;
            int gr = blockRow + row;
            if (gr >= M) gr = M - 1;
            cpa16(smem_u32(&As[st][row][q * 4]), &A[(size_t)gr * K + k0 + q * 4]);
        }
    };
    auto loadB = [&](int c, int st) {
        int k0 = c * BK;
        constexpr int CH = BK * BN / 4;
#pragma unroll
        for (int l = 0; l < CH / 256; l++) {
            int f = tid + l * 256;
            int kr = f / (BN / 4), q = f % (BN / 4);
            cpa16(smem_u32(&Bs[st][kr][q * 4]), &B[(size_t)(k0 + kr) * BN + q * 4]);
        }
    };

    loadA(0, 0);
    loadB(0, 0);
    asm volatile("cp.async.commit_group;");

    for (int c = 0; c < nch; c++) {
        int st = c & 1;
        if (c + 1 < nch) {
            loadA(c + 1, (c + 1) & 1);
            loadB(c + 1, (c + 1) & 1);
            asm volatile("cp.async.commit_group;");
            asm volatile("cp.async.wait_group 1;");
        } else {
            asm volatile("cp.async.wait_group 0;");
        }
        __syncthreads();

#pragma unroll
        for (int k4 = 0; k4 < BK; k4 += 4) {
            float4 a4[8];
#pragma unroll
            for (int i = 0; i < 8; i++)
                a4[i] = *reinterpret_cast<const float4*>(&As[st][ty * 8 + i][k4]);
#pragma unroll
            for (int kk = 0; kk < 4; kk++) {
                ull b2[TN / 2];
#pragma unroll
                for (int g = 0; g < NG; g++) {
                    F4U bu;
                    bu.f = *reinterpret_cast<const float4*>(&Bs[st][k4 + kk][g * 64 + tx * 4]);
                    b2[g * 2 + 0] = bu.u[0];
                    b2[g * 2 + 1] = bu.u[1];
                }
#pragma unroll
                for (int i = 0; i < 8; i++) {
                    float av = (kk == 0) ? a4[i].x : (kk == 1) ? a4[i].y : (kk == 2) ? a4[i].z : a4[i].w;
                    ull a2 = splat2(av);
#pragma unroll
                    for (int j = 0; j < TN / 2; j++) fma2(acc[i][j], a2, b2[j]);
                }
            }
        }
        __syncthreads();
    }

    // ---- per-row epilogue ----
#pragma unroll
    for (int i = 0; i < 8; i++) {
        int r = blockRow + ty * 8 + i;
        float af[TN];
#pragma unroll
        for (int j = 0; j < TN / 2; j++) upk2(acc[i][j], af[2 * j], af[2 * j + 1]);

        if (s_out) {
            if (BN == 128) {
                float ps0 = 0.f, pt0 = 0.f, ps1 = 0.f, pt1 = 0.f;
#pragma unroll
                for (int j = 0; j < 4; j++) {
                    int c0 = tx * 4 + j, c1 = 64 + tx * 4 + j;
                    ps0 += af[j] * sh_att[c0];
                    pt0 += af[j] * sh_att[BN + c0];
                    ps1 += af[4 + j] * sh_att[c1];
                    pt1 += af[4 + j] * sh_att[BN + c1];
                }
#pragma unroll
                for (int off = 8; off; off >>= 1) {
                    ps0 += __shfl_xor_sync(0xFFFFFFFFu, ps0, off);
                    pt0 += __shfl_xor_sync(0xFFFFFFFFu, pt0, off);
                    ps1 += __shfl_xor_sync(0xFFFFFFFFu, ps1, off);
                    pt1 += __shfl_xor_sync(0xFFFFFFFFu, pt1, off);
                }
                if (tx == 0 && r < M) {
                    s_out[r * 2 + 0] = ps0;
                    s_out[r * 2 + 1] = ps1;
                    t_out[r * 2 + 0] = pt0;
                    t_out[r * 2 + 1] = pt1;
                }
            } else {
                float ps = 0.f, pt = 0.f;
#pragma unroll
                for (int j = 0; j < 4; j++) {
                    int col = tx * 4 + j;
                    ps += af[j] * sh_att[col];
                    pt += af[j] * sh_att[BN + col];
                }
#pragma unroll
                for (int off = 8; off; off >>= 1) {
                    ps += __shfl_xor_sync(0xFFFFFFFFu, ps, off);
                    pt += __shfl_xor_sync(0xFFFFFFFFu, pt, off);
                }
                if (tx == 0 && r < M) {
                    s_out[r] = ps;
                    t_out[r] = pt;
                }
            }
        }

        if (r < M) {
#pragma unroll
            for (int g = 0; g < NG; g++) {
                int col = g * 64 + tx * 4;
                float4 v;
                v.x = af[g * 4 + 0];
                v.y = af[g * 4 + 1];
                v.z = af[g * 4 + 2];
                v.w = af[g * 4 + 3];
                if (bias) {
                    v.x += bias[col + 0]; v.y += bias[col + 1];
                    v.z += bias[col + 2]; v.w += bias[col + 3];
                }
                if (relu) {
                    v.x = fmaxf(v.x, 0.f); v.y = fmaxf(v.y, 0.f);
                    v.z = fmaxf(v.z, 0.f); v.w = fmaxf(v.w, 0.f);
                }
                if (C2) {
                    float* dst = (g == 0) ? C : C2;
                    *reinterpret_cast<float4*>(&dst[(size_t)r * 64 + tx * 4]) = v;
                } else {
                    *reinterpret_cast<float4*>(&C[(size_t)r * BN + col]) = v;
                }
            }
        }
    }
}

// ---------------- GAT aggregation: one WARP per dst node ----------------
// Gather uses one LDG.128 per lane per edge: lane l owns cols [4l, 4l+4).
// For H=2: lanes 0-15 -> head0 (cols 0-63), lanes 16-31 -> head1 (cols 64-127).
// For H=1: lane l owns cols [2l, 2l+2) via LDG.64.
template <int H, bool RELU>
__global__ void __launch_bounds__(256) k_aggw(const float* __restrict__ hin,
                                              const float* __restrict__ s,
                                              const float* __restrict__ t,
                                              const int* __restrict__ rowptr,
                                              const int* __restrict__ col,
                                              const float* __restrict__ bias,
                                              float* __restrict__ out, int n) {
    constexpr int W = H * 64;
    int node = (blockIdx.x * 256 + threadIdx.x) >> 5;
    if (node >= n) return;
    int lane = threadIdx.x & 31;
    int start = rowptr[node];
    int deg = rowptr[node + 1] - start;

    float tn[H];
#pragma unroll
    for (int h = 0; h < H; h++) tn[h] = t[node * H + h];

    float4 acc = make_float4(0.f, 0.f, 0.f, 0.f);   // H==2: 4 floats; H==1: use .x/.y

    if (deg <= 32) {
        // ---- single-chunk fast path ----
        int src = 0;
        float e0 = -1e30f, e1 = -1e30f;
        bool act = lane < deg;
        if (act) {
            src = col[start + lane];
            if (H == 2) {
                float2 sv = *reinterpret_cast<const float2*>(&s[src * 2]);
                e0 = sv.x + tn[0];
                e0 = e0 > 0.f ? e0 : NEG_SLOPE * e0;
                e1 = sv.y + tn[1];
                e1 = e1 > 0.f ? e1 : NEG_SLOPE * e1;
            } else {
                e0 = s[src] + tn[0];
                e0 = e0 > 0.f ? e0 : NEG_SLOPE * e0;
            }
        }
        float m0 = e0, m1 = e1;
#pragma unroll
        for (int off = 16; off; off >>= 1) {
            m0 = fmaxf(m0, __shfl_xor_sync(0xFFFFFFFFu, m0, off));
            if (H == 2) m1 = fmaxf(m1, __shfl_xor_sync(0xFFFFFFFFu, m1, off));
        }
        float x0 = act ? __expf(e0 - m0) : 0.f;
        float x1 = (H == 2 && act) ? __expf(e1 - m1) : 0.f;
        float s0 = x0, s1 = x1;
#pragma unroll
        for (int off = 16; off; off >>= 1) {
            s0 += __shfl_xor_sync(0xFFFFFFFFu, s0, off);
            if (H == 2) s1 += __shfl_xor_sync(0xFFFFFFFFu, s1, off);
        }
        float al0 = x0 / (s0 + 1e-16f);
        float al1 = (H == 2) ? x1 / (s1 + 1e-16f) : al0;

        for (int e2 = 0; e2 < deg; e2++) {
            int sb = __shfl_sync(0xFFFFFFFFu, src, e2);
            float a0 = __shfl_sync(0xFFFFFFFFu, al0, e2);
            if (H == 2) {
                float a1 = __shfl_sync(0xFFFFFFFFu, al1, e2);
                float a = (lane < 16) ? a0 : a1;
                float4 hv = *reinterpret_cast<const float4*>(hin + (size_t)sb * 128 + lane * 4);
                acc.x = fmaf(a, hv.x, acc.x);
                acc.y = fmaf(a, hv.y, acc.y);
                acc.z = fmaf(a, hv.z, acc.z);
                acc.w = fmaf(a, hv.w, acc.w);
            } else {
                float2 hv = *reinterpret_cast<const float2*>(hin + (size_t)sb * 64 + lane * 2);
                acc.x = fmaf(a0, hv.x, acc.x);
                acc.y = fmaf(a0, hv.y, acc.y);
            }
        }
    } else {
        // ---- general path: online softmax + rescan ----
        float m[H], sm[H];
#pragma unroll
        for (int h = 0; h < H; h++) { m[h] = -1e30f; sm[h] = 0.f; }
        for (int k = lane; k < deg; k += 32) {
            int src = col[start + k];
            float e[H];
            if (H == 2) {
                float2 sv = *reinterpret_cast<const float2*>(&s[src * 2]);
                e[0] = sv.x + tn[0];
                e[1] = sv.y + tn[1];
            } else {
                e[0] = s[src] + tn[0];
            }
#pragma unroll
            for (int h = 0; h < H; h++) {
                float eh = e[h];
                eh = eh > 0.f ? eh : NEG_SLOPE * eh;
                float old = m[h];
                float nm = fmaxf(old, eh);
                sm[h] = sm[h] * __expf(old - nm) + __expf(eh - nm);
                m[h] = nm;
            }
        }
        float inv[H];
#pragma unroll
        for (int h = 0; h < H; h++) {
#pragma unroll
            for (int off = 16; off; off >>= 1) {
                float mo = __shfl_xor_sync(0xFFFFFFFFu, m[h], off);
                float so = __shfl_xor_sync(0xFFFFFFFFu, sm[h], off);
                float nm = fmaxf(m[h], mo);
                sm[h] = sm[h] * __expf(m[h] - nm) + so * __expf(mo - nm);
                m[h] = nm;
            }
            inv[h] = 1.f / (sm[h] + 1e-16f);
        }

        for (int base = 0; base < deg; base += 32) {
            int k = base + lane;
            int src = 0;
            float al0 = 0.f, al1 = 0.f;
            if (k < deg) {
                src = col[start + k];
                if (H == 2) {
                    float2 sv = *reinterpret_cast<const float2*>(&s[src * 2]);
                    float e0 = sv.x + tn[0];
                    e0 = e0 > 0.f ? e0 : NEG_SLOPE * e0;
                    al0 = __expf(e0 - m[0]) * inv[0];
                    float e1 = sv.y + tn[1];
                    e1 = e1 > 0.f ? e1 : NEG_SLOPE * e1;
                    al1 = __expf(e1 - m[1]) * inv[1];
                } else {
                    float e = s[src] + tn[0];
                    e = e > 0.f ? e : NEG_SLOPE * e;
                    al0 = __expf(e - m[0]) * inv[0];
                }
            }
            int nk = min(32, deg - base);
            for (int e2 = 0; e2 < nk; e2++) {
                int sb = __shfl_sync(0xFFFFFFFFu, src, e2);
                float a0 = __shfl_sync(0xFFFFFFFFu, al0, e2);
                if (H == 2) {
                    float a1 = __shfl_sync(0xFFFFFFFFu, al1, e2);
                    float a = (lane < 16) ? a0 : a1;
                    float4 hv = *reinterpret_cast<const float4*>(hin + (size_t)sb * 128 + lane * 4);
                    acc.x = fmaf(a, hv.x, acc.x);
                    acc.y = fmaf(a, hv.y, acc.y);
                    acc.z = fmaf(a, hv.z, acc.z);
                    acc.w = fmaf(a, hv.w, acc.w);
                } else {
                    float2 hv = *reinterpret_cast<const float2*>(hin + (size_t)sb * 64 + lane * 2);
                    acc.x = fmaf(a0, hv.x, acc.x);
                    acc.y = fmaf(a0, hv.y, acc.y);
                }
            }
        }
    }

    if (H == 2) {
        float4 bv = *reinterpret_cast<const float4*>(bias + lane * 4);
        float4 v;
        v.x = acc.x + bv.x;
        v.y = acc.y + bv.y;
        v.z = acc.z + bv.z;
        v.w = acc.w + bv.w;
        if (RELU) {
            v.x = fmaxf(v.x, 0.f); v.y = fmaxf(v.y, 0.f);
            v.z = fmaxf(v.z, 0.f); v.w = fmaxf(v.w, 0.f);
        }
        *reinterpret_cast<float4*>(out + (size_t)node * 128 + lane * 4) = v;
    } else {
        float2 bv = *reinterpret_cast<const float2*>(bias + lane * 2);
        float2 v;
        v.x = acc.x + bv.x;
        v.y = acc.y + bv.y;
        if (RELU) {
            v.x = fmaxf(v.x, 0.f);
            v.y = fmaxf(v.y, 0.f);
        }
        *reinterpret_cast<float2*>(out + (size_t)node * 64 + lane * 2) = v;
    }
}

// ---------------- host launch ----------------
extern "C" void kernel_launch(void* const* d_in, const int* in_sizes, int n_in,
                              void* d_out, int out_size) {
    const float* x     = (const float*)d_in[0];
    const int*   ei    = (const int*)d_in[1];
    const float* W0    = (const float*)d_in[2];
    const float* as0   = (const float*)d_in[3];
    const float* ad0   = (const float*)d_in[4];
    const float* b0    = (const float*)d_in[5];
    const float* W1    = (const float*)d_in[6];
    const float* as1   = (const float*)d_in[7];
    const float* ad1   = (const float*)d_in[8];
    const float* b1    = (const float*)d_in[9];
    const float* W2    = (const float*)d_in[10];
    const float* as2   = (const float*)d_in[11];
    const float* ad2   = (const float*)d_in[12];
    const float* b2    = (const float*)d_in[13];
    const float* Wv    = (const float*)d_in[14];
    const float* bv    = (const float*)d_in[15];
    const float* Wt    = (const float*)d_in[16];
    const float* bt    = (const float*)d_in[17];

    int N = in_sizes[0] / 512;
    int E = in_sizes[1] / 2;

    float* out = (float*)d_out;
    float* h_out = out;
    float* vis = out + (size_t)N * 64;
    float* txt = out + (size_t)N * 64 * 2;

    float *h0, *h1, *sA, *tA, *Wcat, *bcat;
    int *deg, *rowptr, *cursor, *colA, *bsum, *bexc;
    cudaGetSymbolAddress((void**)&h0, g_h0);
    cudaGetSymbolAddress((void**)&h1, g_h1);
    cudaGetSymbolAddress((void**)&sA, g_s);
    cudaGetSymbolAddress((void**)&tA, g_t);
    cudaGetSymbolAddress((void**)&deg, g_deg);
    cudaGetSymbolAddress((void**)&rowptr, g_rowptr);
    cudaGetSymbolAddress((void**)&cursor, g_cursor);
    cudaGetSymbolAddress((void**)&colA, g_col);
    cudaGetSymbolAddress((void**)&bsum, g_bsum);
    cudaGetSymbolAddress((void**)&bexc, g_bexc);
    cudaGetSymbolAddress((void**)&Wcat, g_Wcat);
    cudaGetSymbolAddress((void**)&bcat, g_bcat);

    static cudaStream_t s2 = nullptr;
    static cudaEvent_t evFork = nullptr, evJoin = nullptr;
    if (!s2) {
        cudaStreamCreateWithFlags(&s2, cudaStreamNonBlocking);
        cudaEventCreateWithFlags(&evFork, cudaEventDisableTiming);
        cudaEventCreateWithFlags(&evJoin, cudaEventDisableTiming);
    }

    int nb = (N + 255) / 256;
    int gblk = (N + 127) / 128;
    int wgrid = (N * 32 + 255) / 256;

    // ---- fork: CSR build + Wcat prep on side stream ----
    cudaEventRecord(evFork, 0);
    cudaStreamWaitEvent(s2, evFork, 0);
    k_init_deg<<<nb, 256, 0, s2>>>(deg, N);
    k_hist<<<(E + 255) / 256, 256, 0, s2>>>(ei, E, deg);
    k_blocksums<<<nb, 256, 0, s2>>>(deg, bsum, N);
    k_scan_top<<<1, 256, 0, s2>>>(bsum, bexc, nb);
    k_scan_apply<<<nb, 256, 0, s2>>>(deg, bexc, rowptr, cursor, colA, N);
    k_scatter<<<(E + 255) / 256, 256, 0, s2>>>(ei, E, cursor, colA);
    k_prep<<<(64 * 128 + 255) / 256, 256, 0, s2>>>(Wv, bv, Wt, bt, Wcat, bcat);
    cudaEventRecord(evJoin, s2);

    // ---- main stream: layer-0 GEMM concurrently ----
    k_gemm<128><<<gblk, 256>>>(x, W0, h0, nullptr, N, 512, nullptr, 0, as0, ad0, sA, tA);

    // ---- join ----
    cudaStreamWaitEvent(0, evJoin, 0);

    // ---- layer 0 aggregation ----
    k_aggw<2, true><<<wgrid, 256>>>(h0, sA, tA, rowptr, colA, b0, h1, N);

    // ---- layer 1 ----
    k_gemm<128><<<gblk, 256>>>(h1, W1, h0, nullptr, N, 128, nullptr, 0, as1, ad1, sA, tA);
    k_aggw<2, true><<<wgrid, 256>>>(h0, sA, tA, rowptr, colA, b1, h1, N);

    // ---- layer 2 (heads=1, no relu) ----
    k_gemm<64><<<gblk, 256>>>(h1, W2, h0, nullptr, N, 128, nullptr, 0, as2, ad2, sA, tA);
    k_aggw<1, false><<<wgrid, 256>>>(h0, sA, tA, rowptr, colA, b2, h_out, N);

    // ---- MLP heads: one combined GEMM with split store ----
    k_gemm<128><<<gblk, 256>>>(h_out, Wcat, vis, txt, N, 64, bcat, 1,
                               nullptr, nullptr, nullptr, nullptr);
}

// round 15
// speedup vs baseline: 1.1110x; 1.0108x over previous
#include <cuda_runtime.h>
#include <cstdint>

#define NNODES 50000
#define NEDGES 800000
#define TOTEDGES (NEDGES + NNODES)
#define NEG_SLOPE 0.2f

// ---------------- scratch (allocation-free: device globals) ----------------
__device__ float g_h0[(size_t)NNODES * 128];
__device__ float g_h1[(size_t)NNODES * 128];
__device__ float g_s[NNODES * 2];
__device__ float g_t[NNODES * 2];
__device__ int   g_deg[NNODES];
__device__ int   g_rowptr[NNODES + 1];
__device__ int   g_cursor[NNODES];
__device__ int   g_col[TOTEDGES];
__device__ int   g_bsum[256];
__device__ int   g_bexc[256];
__device__ float g_Wcat[64 * 128];
__device__ float g_bcat[128];

// ---------------- helpers ----------------
__device__ __forceinline__ uint32_t smem_u32(const void* p) {
    return (uint32_t)__cvta_generic_to_shared(p);
}
typedef unsigned long long ull;
union F4U { float4 f; ull u[2]; };
__device__ __forceinline__ ull splat2(float x) {
    ull r;
    asm("mov.b64 %0, {%1, %1};" : "=l"(r) : "f"(x));
    return r;
}
__device__ __forceinline__ void fma2(ull& d, ull a, ull b) {
    asm("fma.rn.f32x2 %0, %1, %2, %3;" : "=l"(d) : "l"(a), "l"(b), "l"(d));
}
__device__ __forceinline__ void upk2(ull v, float& lo, float& hi) {
    asm("mov.b64 {%0, %1}, %2;" : "=f"(lo), "=f"(hi) : "l"(v));
}
__device__ __forceinline__ void cpa16(uint32_t dst, const void* src) {
    asm volatile("cp.async.cg.shared.global [%0], [%1], 16;" :: "r"(dst), "l"(src));
}

// ---------------- CSR build ----------------
__global__ void k_init_deg(int* __restrict__ deg, int n) {
    int i = blockIdx.x * blockDim.x + threadIdx.x;
    if (i < n) deg[i] = 1;
}
__global__ void k_hist(const int* __restrict__ ei, int e, int* __restrict__ deg) {
    int i = blockIdx.x * blockDim.x + threadIdx.x;
    if (i < e) atomicAdd(&deg[ei[e + i]], 1);
}
__global__ void k_blocksums(const int* __restrict__ deg, int* __restrict__ bsum, int n) {
    __shared__ int wred[8];
    int i = blockIdx.x * 256 + threadIdx.x;
    int v = (i < n) ? deg[i] : 0;
    int lane = threadIdx.x & 31, w = threadIdx.x >> 5;
#pragma unroll
    for (int off = 16; off; off >>= 1) v += __shfl_xor_sync(0xFFFFFFFFu, v, off);
    if (lane == 0) wred[w] = v;
    __syncthreads();
    if (threadIdx.x == 0) {
        int s = 0;
#pragma unroll
        for (int k = 0; k < 8; k++) s += wred[k];
        bsum[blockIdx.x] = s;
    }
}
__global__ void k_scan_top(const int* __restrict__ bsum, int* __restrict__ bexc, int nb) {
    __shared__ int wred[8];
    int tid = threadIdx.x, lane = tid & 31, w = tid >> 5;
    int v = (tid < nb) ? bsum[tid] : 0;
    int x = v;
#pragma unroll
    for (int off = 1; off < 32; off <<= 1) {
        int y = __shfl_up_sync(0xFFFFFFFFu, x, off);
        if (lane >= off) x += y;
    }
    if (lane == 31) wred[w] = x;
    __syncthreads();
    if (w == 0) {
        int sv = (lane < 8) ? wred[lane] : 0;
#pragma unroll
        for (int off = 1; off < 8; off <<= 1) {
            int y = __shfl_up_sync(0xFFFFFFFFu, sv, off);
            if (lane >= off) sv += y;
        }
        if (lane < 8) wred[lane] = sv;
    }
    __syncthreads();
    int woff = (w > 0) ? wred[w - 1] : 0;
    if (tid < nb) bexc[tid] = x + woff - v;
}
__global__ void k_scan_apply(const int* __restrict__ deg, const int* __restrict__ bexc,
                             int* __restrict__ rowptr, int* __restrict__ cursor,
                             int* __restrict__ col, int n) {
    __shared__ int wred[8];
    int i = blockIdx.x * 256 + threadIdx.x;
    int tid = threadIdx.x, lane = tid & 31, w = tid >> 5;
    int v = (i < n) ? deg[i] : 0;
    int x = v;
#pragma unroll
    for (int off = 1; off < 32; off <<= 1) {
        int y = __shfl_up_sync(0xFFFFFFFFu, x, off);
        if (lane >= off) x += y;
    }
    if (lane == 31) wred[w] = x;
    __syncthreads();
    if (w == 0) {
        int sv = (lane < 8) ? wred[lane] : 0;
#pragma unroll
        for (int off = 1; off < 8; off <<= 1) {
            int y = __shfl_up_sync(0xFFFFFFFFu, sv, off);
            if (lane >= off) sv += y;
        }
        if (lane < 8) wred[lane] = sv;
    }
    __syncthreads();
    int woff = (w > 0) ? wred[w - 1] : 0;
    if (i < n) {
        int incl = x + woff + bexc[blockIdx.x];
        rowptr[i + 1] = incl;
        int p = incl - v;
        col[p] = i;
        cursor[i] = p + 1;
        if (i == 0) rowptr[0] = 0;
    }
}
__global__ void k_scatter(const int* __restrict__ ei, int e, int* __restrict__ cursor,
                          int* __restrict__ col) {
    int i = blockIdx.x * blockDim.x + threadIdx.x;
    if (i < e) {
        int s = ei[i];
        int d = ei[e + i];
        int p = atomicAdd(&cursor[d], 1);
        col[p] = s;
    }
}

// ---------------- Wcat prep ----------------
__global__ void k_prep(const float* __restrict__ Wv, const float* __restrict__ bv,
                       const float* __restrict__ Wt, const float* __restrict__ bt,
                       float* __restrict__ Wcat, float* __restrict__ bcat) {
    int i = blockIdx.x * blockDim.x + threadIdx.x;
    if (i < 64 * 128) {
        int k = i >> 7, n = i & 127;
        Wcat[i] = (n < 64) ? Wv[k * 64 + n] : Wt[k * 64 + (n - 64)];
    }
    if (i < 128) bcat[i] = (i < 64) ? bv[i] : bt[i - 64];
}

// ---------------- f32x2 GEMM (R8/R10 proven shape) ----------------
template <int BN>
__global__ void __launch_bounds__(256, 2) k_gemm(
    const float* __restrict__ A, const float* __restrict__ B,
    float* __restrict__ C, float* __restrict__ C2, int M, int K,
    const float* __restrict__ bias, int relu,
    const float* __restrict__ a_src, const float* __restrict__ a_dst,
    float* __restrict__ s_out, float* __restrict__ t_out)
{
    constexpr int BM = 128, BK = 16, TN = BN / 16;
    constexpr int NG = BN / 64;
    __shared__ float As[2][BM][BK];
    __shared__ float Bs[2][BK][BN];
    __shared__ float sh_att[2 * BN];

    int tid = threadIdx.x;
    int tx = tid & 15, ty = tid >> 4;
    int blockRow = blockIdx.x * BM;

    if (a_src) {
        if (tid < BN) sh_att[tid] = a_src[tid];
        else if (tid < 2 * BN) sh_att[tid] = a_dst[tid - BN];
    }

    ull acc[8][TN / 2];
#pragma unroll
    for (int i = 0; i < 8; i++)
#pragma unroll
        for (int j = 0; j < TN / 2; j++) acc[i][j] = 0ull;

    int nch = K / BK;

    auto loadA = [&](int c, int st) {
        int k0 = c * BK;
#pragma unroll
        for (int l = 0; l < 2; l++) {
            int f = tid + l * 256;
            int row = f >> 2, q = f & 3;
            int gr = blockRow + row;
            if (gr >= M) gr = M - 1;
            cpa16(smem_u32(&As[st][row][q * 4]), &A[(size_t)gr * K + k0 + q * 4]);
        }
    };
    auto loadB = [&](int c, int st) {
        int k0 = c * BK;
        constexpr int CH = BK * BN / 4;
#pragma unroll
        for (int l = 0; l < CH / 256; l++) {
            int f = tid + l * 256;
            int kr = f / (BN / 4), q = f % (BN / 4);
            cpa16(smem_u32(&Bs[st][kr][q * 4]), &B[(size_t)(k0 + kr) * BN + q * 4]);
        }
    };

    loadA(0, 0);
    loadB(0, 0);
    asm volatile("cp.async.commit_group;");

    for (int c = 0; c < nch; c++) {
        int st = c & 1;
        if (c + 1 < nch) {
            loadA(c + 1, (c + 1) & 1);
            loadB(c + 1, (c + 1) & 1);
            asm volatile("cp.async.commit_group;");
            asm volatile("cp.async.wait_group 1;");
        } else {
            asm volatile("cp.async.wait_group 0;");
        }
        __syncthreads();

#pragma unroll
        for (int k4 = 0; k4 < BK; k4 += 4) {
            float4 a4[8];
#pragma unroll
            for (int i = 0; i < 8; i++)
                a4[i] = *reinterpret_cast<const float4*>(&As[st][ty * 8 + i][k4]);
#pragma unroll
            for (int kk = 0; kk < 4; kk++) {
                ull b2[TN / 2];
#pragma unroll
                for (int g = 0; g < NG; g++) {
                    F4U bu;
                    bu.f = *reinterpret_cast<const float4*>(&Bs[st][k4 + kk][g * 64 + tx * 4]);
                    b2[g * 2 + 0] = bu.u[0];
                    b2[g * 2 + 1] = bu.u[1];
                }
#pragma unroll
                for (int i = 0; i < 8; i++) {
                    float av = (kk == 0) ? a4[i].x : (kk == 1) ? a4[i].y : (kk == 2) ? a4[i].z : a4[i].w;
                    ull a2 = splat2(av);
#pragma unroll
                    for (int j = 0; j < TN / 2; j++) fma2(acc[i][j], a2, b2[j]);
                }
            }
        }
        __syncthreads();
    }

    // ---- per-row epilogue ----
#pragma unroll
    for (int i = 0; i < 8; i++) {
        int r = blockRow + ty * 8 + i;
        float af[TN];
#pragma unroll
        for (int j = 0; j < TN / 2; j++) upk2(acc[i][j], af[2 * j], af[2 * j + 1]);

        if (s_out) {
            if (BN == 128) {
                float ps0 = 0.f, pt0 = 0.f, ps1 = 0.f, pt1 = 0.f;
#pragma unroll
                for (int j = 0; j < 4; j++) {
                    int c0 = tx * 4 + j, c1 = 64 + tx * 4 + j;
                    ps0 += af[j] * sh_att[c0];
                    pt0 += af[j] * sh_att[BN + c0];
                    ps1 += af[4 + j] * sh_att[c1];
                    pt1 += af[4 + j] * sh_att[BN + c1];
                }
#pragma unroll
                for (int off = 8; off; off >>= 1) {
                    ps0 += __shfl_xor_sync(0xFFFFFFFFu, ps0, off);
                    pt0 += __shfl_xor_sync(0xFFFFFFFFu, pt0, off);
                    ps1 += __shfl_xor_sync(0xFFFFFFFFu, ps1, off);
                    pt1 += __shfl_xor_sync(0xFFFFFFFFu, pt1, off);
                }
                if (tx == 0 && r < M) {
                    s_out[r * 2 + 0] = ps0;
                    s_out[r * 2 + 1] = ps1;
                    t_out[r * 2 + 0] = pt0;
                    t_out[r * 2 + 1] = pt1;
                }
            } else {
                float ps = 0.f, pt = 0.f;
#pragma unroll
                for (int j = 0; j < 4; j++) {
                    int col = tx * 4 + j;
                    ps += af[j] * sh_att[col];
                    pt += af[j] * sh_att[BN + col];
                }
#pragma unroll
                for (int off = 8; off; off >>= 1) {
                    ps += __shfl_xor_sync(0xFFFFFFFFu, ps, off);
                    pt += __shfl_xor_sync(0xFFFFFFFFu, pt, off);
                }
                if (tx == 0 && r < M) {
                    s_out[r] = ps;
                    t_out[r] = pt;
                }
            }
        }

        if (r < M) {
#pragma unroll
            for (int g = 0; g < NG; g++) {
                int col = g * 64 + tx * 4;
                float4 v;
                v.x = af[g * 4 + 0];
                v.y = af[g * 4 + 1];
                v.z = af[g * 4 + 2];
                v.w = af[g * 4 + 3];
                if (bias) {
                    v.x += bias[col + 0]; v.y += bias[col + 1];
                    v.z += bias[col + 2]; v.w += bias[col + 3];
                }
                if (relu) {
                    v.x = fmaxf(v.x, 0.f); v.y = fmaxf(v.y, 0.f);
                    v.z = fmaxf(v.z, 0.f); v.w = fmaxf(v.w, 0.f);
                }
                if (C2) {
                    float* dst = (g == 0) ? C : C2;
                    *reinterpret_cast<float4*>(&dst[(size_t)r * 64 + tx * 4]) = v;
                } else {
                    *reinterpret_cast<float4*>(&C[(size_t)r * BN + col]) = v;
                }
            }
        }
    }
}

// ---------------- GAT aggregation: one WARP per dst node ----------------
// One LDG.128 (H=2) / LDG.64 (H=1) per lane per edge; gather loop pipelined
// by 4 edges (4 independent loads in flight -> MLP=4 hides L2 latency).
template <int H, bool RELU>
__global__ void __launch_bounds__(256) k_aggw(const float* __restrict__ hin,
                                              const float* __restrict__ s,
                                              const float* __restrict__ t,
                                              const int* __restrict__ rowptr,
                                              const int* __restrict__ col,
                                              const float* __restrict__ bias,
                                              float* __restrict__ out, int n) {
    int node = (blockIdx.x * 256 + threadIdx.x) >> 5;
    if (node >= n) return;
    int lane = threadIdx.x & 31;
    int start = rowptr[node];
    int deg = rowptr[node + 1] - start;

    float tn[H];
#pragma unroll
    for (int h = 0; h < H; h++) tn[h] = t[node * H + h];

    float4 acc = make_float4(0.f, 0.f, 0.f, 0.f);

    // pipelined gather over [0, cnt) edges, alphas/srcs register-resident
    auto gather = [&](int src, float al0, float al1, int cnt) {
        int e2 = 0;
        for (; e2 + 4 <= cnt; e2 += 4) {
            int sb0 = __shfl_sync(0xFFFFFFFFu, src, e2 + 0);
            int sb1 = __shfl_sync(0xFFFFFFFFu, src, e2 + 1);
            int sb2 = __shfl_sync(0xFFFFFFFFu, src, e2 + 2);
            int sb3 = __shfl_sync(0xFFFFFFFFu, src, e2 + 3);
            float p0 = __shfl_sync(0xFFFFFFFFu, al0, e2 + 0);
            float p1 = __shfl_sync(0xFFFFFFFFu, al0, e2 + 1);
            float p2 = __shfl_sync(0xFFFFFFFFu, al0, e2 + 2);
            float p3 = __shfl_sync(0xFFFFFFFFu, al0, e2 + 3);
            if (H == 2) {
                float q0 = __shfl_sync(0xFFFFFFFFu, al1, e2 + 0);
                float q1 = __shfl_sync(0xFFFFFFFFu, al1, e2 + 1);
                float q2 = __shfl_sync(0xFFFFFFFFu, al1, e2 + 2);
                float q3 = __shfl_sync(0xFFFFFFFFu, al1, e2 + 3);
                float a0 = (lane < 16) ? p0 : q0;
                float a1 = (lane < 16) ? p1 : q1;
                float a2 = (lane < 16) ? p2 : q2;
                float a3 = (lane < 16) ? p3 : q3;
                float4 v0 = *reinterpret_cast<const float4*>(hin + (size_t)sb0 * 128 + lane * 4);
                float4 v1 = *reinterpret_cast<const float4*>(hin + (size_t)sb1 * 128 + lane * 4);
                float4 v2 = *reinterpret_cast<const float4*>(hin + (size_t)sb2 * 128 + lane * 4);
                float4 v3 = *reinterpret_cast<const float4*>(hin + (size_t)sb3 * 128 + lane * 4);
                acc.x = fmaf(a0, v0.x, acc.x); acc.y = fmaf(a0, v0.y, acc.y);
                acc.z = fmaf(a0, v0.z, acc.z); acc.w = fmaf(a0, v0.w, acc.w);
                acc.x = fmaf(a1, v1.x, acc.x); acc.y = fmaf(a1, v1.y, acc.y);
                acc.z = fmaf(a1, v1.z, acc.z); acc.w = fmaf(a1, v1.w, acc.w);
                acc.x = fmaf(a2, v2.x, acc.x); acc.y = fmaf(a2, v2.y, acc.y);
                acc.z = fmaf(a2, v2.z, acc.z); acc.w = fmaf(a2, v2.w, acc.w);
                acc.x = fmaf(a3, v3.x, acc.x); acc.y = fmaf(a3, v3.y, acc.y);
                acc.z = fmaf(a3, v3.z, acc.z); acc.w = fmaf(a3, v3.w, acc.w);
            } else {
                float2 v0 = *reinterpret_cast<const float2*>(hin + (size_t)sb0 * 64 + lane * 2);
                float2 v1 = *reinterpret_cast<const float2*>(hin + (size_t)sb1 * 64 + lane * 2);
                float2 v2 = *reinterpret_cast<const float2*>(hin + (size_t)sb2 * 64 + lane * 2);
                float2 v3 = *reinterpret_cast<const float2*>(hin + (size_t)sb3 * 64 + lane * 2);
                acc.x = fmaf(p0, v0.x, acc.x); acc.y = fmaf(p0, v0.y, acc.y);
                acc.x = fmaf(p1, v1.x, acc.x); acc.y = fmaf(p1, v1.y, acc.y);
                acc.x = fmaf(p2, v2.x, acc.x); acc.y = fmaf(p2, v2.y, acc.y);
                acc.x = fmaf(p3, v3.x, acc.x); acc.y = fmaf(p3, v3.y, acc.y);
            }
        }
        for (; e2 < cnt; e2++) {
            int sb = __shfl_sync(0xFFFFFFFFu, src, e2);
            float p = __shfl_sync(0xFFFFFFFFu, al0, e2);
            if (H == 2) {
                float q = __shfl_sync(0xFFFFFFFFu, al1, e2);
                float a = (lane < 16) ? p : q;
                float4 hv = *reinterpret_cast<const float4*>(hin + (size_t)sb * 128 + lane * 4);
                acc.x = fmaf(a, hv.x, acc.x); acc.y = fmaf(a, hv.y, acc.y);
                acc.z = fmaf(a, hv.z, acc.z); acc.w = fmaf(a, hv.w, acc.w);
            } else {
                float2 hv = *reinterpret_cast<const float2*>(hin + (size_t)sb * 64 + lane * 2);
                acc.x = fmaf(p, hv.x, acc.x);
                acc.y = fmaf(p, hv.y, acc.y);
            }
        }
    };

    if (deg <= 32) {
        // ---- single-chunk fast path ----
        int src = 0;
        float e0 = -1e30f, e1 = -1e30f;
        bool act = lane < deg;
        if (act) {
            src = col[start + lane];
            if (H == 2) {
                float2 sv = *reinterpret_cast<const float2*>(&s[src * 2]);
                e0 = sv.x + tn[0];
                e0 = e0 > 0.f ? e0 : NEG_SLOPE * e0;
                e1 = sv.y + tn[1];
                e1 = e1 > 0.f ? e1 : NEG_SLOPE * e1;
            } else {
                e0 = s[src] + tn[0];
                e0 = e0 > 0.f ? e0 : NEG_SLOPE * e0;
            }
        }
        float m0 = e0, m1 = e1;
#pragma unroll
        for (int off = 16; off; off >>= 1) {
            m0 = fmaxf(m0, __shfl_xor_sync(0xFFFFFFFFu, m0, off));
            if (H == 2) m1 = fmaxf(m1, __shfl_xor_sync(0xFFFFFFFFu, m1, off));
        }
        float x0 = act ? __expf(e0 - m0) : 0.f;
        float x1 = (H == 2 && act) ? __expf(e1 - m1) : 0.f;
        float s0 = x0, s1 = x1;
#pragma unroll
        for (int off = 16; off; off >>= 1) {
            s0 += __shfl_xor_sync(0xFFFFFFFFu, s0, off);
            if (H == 2) s1 += __shfl_xor_sync(0xFFFFFFFFu, s1, off);
        }
        float al0 = x0 / (s0 + 1e-16f);
        float al1 = (H == 2) ? x1 / (s1 + 1e-16f) : al0;
        gather(src, al0, al1, deg);
    } else {
        // ---- general path: online softmax + rescan ----
        float m[H], sm[H];
#pragma unroll
        for (int h = 0; h < H; h++) { m[h] = -1e30f; sm[h] = 0.f; }
        for (int k = lane; k < deg; k += 32) {
            int src = col[start + k];
            float e[H];
            if (H == 2) {
                float2 sv = *reinterpret_cast<const float2*>(&s[src * 2]);
                e[0] = sv.x + tn[0];
                e[1] = sv.y + tn[1];
            } else {
                e[0] = s[src] + tn[0];
            }
#pragma unroll
            for (int h = 0; h < H; h++) {
                float eh = e[h];
                eh = eh > 0.f ? eh : NEG_SLOPE * eh;
                float old = m[h];
                float nm = fmaxf(old, eh);
                sm[h] = sm[h] * __expf(old - nm) + __expf(eh - nm);
                m[h] = nm;
            }
        }
        float inv[H];
#pragma unroll
        for (int h = 0; h < H; h++) {
#pragma unroll
            for (int off = 16; off; off >>= 1) {
                float mo = __shfl_xor_sync(0xFFFFFFFFu, m[h], off);
                float so = __shfl_xor_sync(0xFFFFFFFFu, sm[h], off);
                float nm = fmaxf(m[h], mo);
                sm[h] = sm[h] * __expf(m[h] - nm) + so * __expf(mo - nm);
                m[h] = nm;
            }
            inv[h] = 1.f / (sm[h] + 1e-16f);
        }

        for (int base = 0; base < deg; base += 32) {
            int k = base + lane;
            int src = 0;
            float al0 = 0.f, al1 = 0.f;
            if (k < deg) {
                src = col[start + k];
                if (H == 2) {
                    float2 sv = *reinterpret_cast<const float2*>(&s[src * 2]);
                    float e0 = sv.x + tn[0];
                    e0 = e0 > 0.f ? e0 : NEG_SLOPE * e0;
                    al0 = __expf(e0 - m[0]) * inv[0];
                    float e1 = sv.y + tn[1];
                    e1 = e1 > 0.f ? e1 : NEG_SLOPE * e1;
                    al1 = __expf(e1 - m[1]) * inv[1];
                } else {
                    float e = s[src] + tn[0];
                    e = e > 0.f ? e : NEG_SLOPE * e;
                    al0 = __expf(e - m[0]) * inv[0];
                }
            }
            gather(src, al0, al1, min(32, deg - base));
        }
    }

    if (H == 2) {
        float4 bv = *reinterpret_cast<const float4*>(bias + lane * 4);
        float4 v;
        v.x = acc.x + bv.x;
        v.y = acc.y + bv.y;
        v.z = acc.z + bv.z;
        v.w = acc.w + bv.w;
        if (RELU) {
            v.x = fmaxf(v.x, 0.f); v.y = fmaxf(v.y, 0.f);
            v.z = fmaxf(v.z, 0.f); v.w = fmaxf(v.w, 0.f);
        }
        *reinterpret_cast<float4*>(out + (size_t)node * 128 + lane * 4) = v;
    } else {
        float2 bv = *reinterpret_cast<const float2*>(bias + lane * 2);
        float2 v;
        v.x = acc.x + bv.x;
        v.y = acc.y + bv.y;
        if (RELU) {
            v.x = fmaxf(v.x, 0.f);
            v.y = fmaxf(v.y, 0.f);
        }
        *reinterpret_cast<float2*>(out + (size_t)node * 64 + lane * 2) = v;
    }
}

// ---------------- host launch ----------------
extern "C" void kernel_launch(void* const* d_in, const int* in_sizes, int n_in,
                              void* d_out, int out_size) {
    const float* x     = (const float*)d_in[0];
    const int*   ei    = (const int*)d_in[1];
    const float* W0    = (const float*)d_in[2];
    const float* as0   = (const float*)d_in[3];
    const float* ad0   = (const float*)d_in[4];
    const float* b0    = (const float*)d_in[5];
    const float* W1    = (const float*)d_in[6];
    const float* as1   = (const float*)d_in[7];
    const float* ad1   = (const float*)d_in[8];
    const float* b1    = (const float*)d_in[9];
    const float* W2    = (const float*)d_in[10];
    const float* as2   = (const float*)d_in[11];
    const float* ad2   = (const float*)d_in[12];
    const float* b2    = (const float*)d_in[13];
    const float* Wv    = (const float*)d_in[14];
    const float* bv    = (const float*)d_in[15];
    const float* Wt    = (const float*)d_in[16];
    const float* bt    = (const float*)d_in[17];

    int N = in_sizes[0] / 512;
    int E = in_sizes[1] / 2;

    float* out = (float*)d_out;
    float* h_out = out;
    float* vis = out + (size_t)N * 64;
    float* txt = out + (size_t)N * 64 * 2;

    float *h0, *h1, *sA, *tA, *Wcat, *bcat;
    int *deg, *rowptr, *cursor, *colA, *bsum, *bexc;
    cudaGetSymbolAddress((void**)&h0, g_h0);
    cudaGetSymbolAddress((void**)&h1, g_h1);
    cudaGetSymbolAddress((void**)&sA, g_s);
    cudaGetSymbolAddress((void**)&tA, g_t);
    cudaGetSymbolAddress((void**)&deg, g_deg);
    cudaGetSymbolAddress((void**)&rowptr, g_rowptr);
    cudaGetSymbolAddress((void**)&cursor, g_cursor);
    cudaGetSymbolAddress((void**)&colA, g_col);
    cudaGetSymbolAddress((void**)&bsum, g_bsum);
    cudaGetSymbolAddress((void**)&bexc, g_bexc);
    cudaGetSymbolAddress((void**)&Wcat, g_Wcat);
    cudaGetSymbolAddress((void**)&bcat, g_bcat);

    static cudaStream_t s2 = nullptr;
    static cudaEvent_t evFork = nullptr, evJoin = nullptr;
    if (!s2) {
        cudaStreamCreateWithFlags(&s2, cudaStreamNonBlocking);
        cudaEventCreateWithFlags(&evFork, cudaEventDisableTiming);
        cudaEventCreateWithFlags(&evJoin, cudaEventDisableTiming);
    }

    int nb = (N + 255) / 256;
    int gblk = (N + 127) / 128;
    int wgrid = (N * 32 + 255) / 256;

    // ---- fork: CSR build + Wcat prep on side stream ----
    cudaEventRecord(evFork, 0);
    cudaStreamWaitEvent(s2, evFork, 0);
    k_init_deg<<<nb, 256, 0, s2>>>(deg, N);
    k_hist<<<(E + 255) / 256, 256, 0, s2>>>(ei, E, deg);
    k_blocksums<<<nb, 256, 0, s2>>>(deg, bsum, N);
    k_scan_top<<<1, 256, 0, s2>>>(bsum, bexc, nb);
    k_scan_apply<<<nb, 256, 0, s2>>>(deg, bexc, rowptr, cursor, colA, N);
    k_scatter<<<(E + 255) / 256, 256, 0, s2>>>(ei, E, cursor, colA);
    k_prep<<<(64 * 128 + 255) / 256, 256, 0, s2>>>(Wv, bv, Wt, bt, Wcat, bcat);
    cudaEventRecord(evJoin, s2);

    // ---- main stream: layer-0 GEMM concurrently ----
    k_gemm<128><<<gblk, 256>>>(x, W0, h0, nullptr, N, 512, nullptr, 0, as0, ad0, sA, tA);

    // ---- join ----
    cudaStreamWaitEvent(0, evJoin, 0);

    // ---- layer 0 aggregation ----
    k_aggw<2, true><<<wgrid, 256>>>(h0, sA, tA, rowptr, colA, b0, h1, N);

    // ---- layer 1 ----
    k_gemm<128><<<gblk, 256>>>(h1, W1, h0, nullptr, N, 128, nullptr, 0, as1, ad1, sA, tA);
    k_aggw<2, true><<<wgrid, 256>>>(h0, sA, tA, rowptr, colA, b1, h1, N);

    // ---- layer 2 (heads=1, no relu) ----
    k_gemm<64><<<gblk, 256>>>(h1, W2, h0, nullptr, N, 128, nullptr, 0, as2, ad2, sA, tA);
    k_aggw<1, false><<<wgrid, 256>>>(h0, sA, tA, rowptr, colA, b2, h_out, N);

    // ---- MLP heads: one combined GEMM with split store ----
    k_gemm<128><<<gblk, 256>>>(h_out, Wcat, vis, txt, N, 64, bcat, 1,
                               nullptr, nullptr, nullptr, nullptr);
}

// round 16
// speedup vs baseline: 1.1281x; 1.0154x over previous
#include <cuda_runtime.h>
#include <cstdint>

#define NNODES 50000
#define NEDGES 800000
#define TOTEDGES (NEDGES + NNODES)
#define NEG_SLOPE 0.2f

// ---------------- scratch (allocation-free: device globals) ----------------
__device__ float g_h0[(size_t)NNODES * 128];
__device__ float g_h1[(size_t)NNODES * 128];
__device__ float g_s[NNODES * 2];
__device__ float g_t[NNODES * 2];
__device__ int   g_deg[NNODES];
__device__ int   g_rowptr[NNODES + 1];
__device__ int   g_cursor[NNODES];
__device__ int   g_col[TOTEDGES];
__device__ int   g_bsum[256];
__device__ int   g_bexc[256];
__device__ float g_Wcat[64 * 128];
__device__ float g_bcat[128];

// ---------------- helpers ----------------
__device__ __forceinline__ uint32_t smem_u32(const void* p) {
    return (uint32_t)__cvta_generic_to_shared(p);
}
typedef unsigned long long ull;
union F4U { float4 f; ull u[2]; };
__device__ __forceinline__ ull splat2(float x) {
    ull r;
    asm("mov.b64 %0, {%1, %1};" : "=l"(r) : "f"(x));
    return r;
}
__device__ __forceinline__ void fma2(ull& d, ull a, ull b) {
    asm("fma.rn.f32x2 %0, %1, %2, %3;" : "=l"(d) : "l"(a), "l"(b), "l"(d));
}
__device__ __forceinline__ void upk2(ull v, float& lo, float& hi) {
    asm("mov.b64 {%0, %1}, %2;" : "=f"(lo), "=f"(hi) : "l"(v));
}
__device__ __forceinline__ void cpa16(uint32_t dst, const void* src) {
    asm volatile("cp.async.cg.shared.global [%0], [%1], 16;" :: "r"(dst), "l"(src));
}

// ---------------- CSR build ----------------
__global__ void k_init_deg(int* __restrict__ deg, int n) {
    int i = blockIdx.x * blockDim.x + threadIdx.x;
    if (i < n) deg[i] = 1;
}
__global__ void k_hist(const int* __restrict__ ei, int e, int* __restrict__ deg) {
    int i = blockIdx.x * blockDim.x + threadIdx.x;
    if (i < e) atomicAdd(&deg[ei[e + i]], 1);
}
__global__ void k_blocksums(const int* __restrict__ deg, int* __restrict__ bsum, int n) {
    __shared__ int wred[8];
    int i = blockIdx.x * 256 + threadIdx.x;
    int v = (i < n) ? deg[i] : 0;
    int lane = threadIdx.x & 31, w = threadIdx.x >> 5;
#pragma unroll
    for (int off = 16; off; off >>= 1) v += __shfl_xor_sync(0xFFFFFFFFu, v, off);
    if (lane == 0) wred[w] = v;
    __syncthreads();
    if (threadIdx.x == 0) {
        int s = 0;
#pragma unroll
        for (int k = 0; k < 8; k++) s += wred[k];
        bsum[blockIdx.x] = s;
    }
}
__global__ void k_scan_top(const int* __restrict__ bsum, int* __restrict__ bexc, int nb) {
    __shared__ int wred[8];
    int tid = threadIdx.x, lane = tid & 31, w = tid >> 5;
    int v = (tid < nb) ? bsum[tid] : 0;
    int x = v;
#pragma unroll
    for (int off = 1; off < 32; off <<= 1) {
        int y = __shfl_up_sync(0xFFFFFFFFu, x, off);
        if (lane >= off) x += y;
    }
    if (lane == 31) wred[w] = x;
    __syncthreads();
    if (w == 0) {
        int sv = (lane < 8) ? wred[lane] : 0;
#pragma unroll
        for (int off = 1; off < 8; off <<= 1) {
            int y = __shfl_up_sync(0xFFFFFFFFu, sv, off);
            if (lane >= off) sv += y;
        }
        if (lane < 8) wred[lane] = sv;
    }
    __syncthreads();
    int woff = (w > 0) ? wred[w - 1] : 0;
    if (tid < nb) bexc[tid] = x + woff - v;
}
__global__ void k_scan_apply(const int* __restrict__ deg, const int* __restrict__ bexc,
                             int* __restrict__ rowptr, int* __restrict__ cursor,
                             int* __restrict__ col, int n) {
    __shared__ int wred[8];
    int i = blockIdx.x * 256 + threadIdx.x;
    int tid = threadIdx.x, lane = tid & 31, w = tid >> 5;
    int v = (i < n) ? deg[i] : 0;
    int x = v;
#pragma unroll
    for (int off = 1; off < 32; off <<= 1) {
        int y = __shfl_up_sync(0xFFFFFFFFu, x, off);
        if (lane >= off) x += y;
    }
    if (lane == 31) wred[w] = x;
    __syncthreads();
    if (w == 0) {
        int sv = (lane < 8) ? wred[lane] : 0;
#pragma unroll
        for (int off = 1; off < 8; off <<= 1) {
            int y = __shfl_up_sync(0xFFFFFFFFu, sv, off);
            if (lane >= off) sv += y;
        }
        if (lane < 8) wred[lane] = sv;
    }
    __syncthreads();
    int woff = (w > 0) ? wred[w - 1] : 0;
    if (i < n) {
        int incl = x + woff + bexc[blockIdx.x];
        rowptr[i + 1] = incl;
        int p = incl - v;
        col[p] = i;
        cursor[i] = p + 1;
        if (i == 0) rowptr[0] = 0;
    }
}
__global__ void k_scatter(const int* __restrict__ ei, int e, int* __restrict__ cursor,
                          int* __restrict__ col) {
    int i = blockIdx.x * blockDim.x + threadIdx.x;
    if (i < e) {
        int s = ei[i];
        int d = ei[e + i];
        int p = atomicAdd(&cursor[d], 1);
        col[p] = s;
    }
}

// ---------------- Wcat prep ----------------
__global__ void k_prep(const float* __restrict__ Wv, const float* __restrict__ bv,
                       const float* __restrict__ Wt, const float* __restrict__ bt,
                       float* __restrict__ Wcat, float* __restrict__ bcat) {
    int i = blockIdx.x * blockDim.x + threadIdx.x;
    if (i < 64 * 128) {
        int k = i >> 7, n = i & 127;
        Wcat[i] = (n < 64) ? Wv[k * 64 + n] : Wt[k * 64 + (n - 64)];
    }
    if (i < 128) bcat[i] = (i < 64) ? bv[i] : bt[i - 64];
}

// ---------------- f32x2 GEMM: 3-stage cp.async pipeline, 1 sync/chunk ----------
template <int BN>
__global__ void __launch_bounds__(256, 2) k_gemm(
    const float* __restrict__ A, const float* __restrict__ B,
    float* __restrict__ C, float* __restrict__ C2, int M, int K,
    const float* __restrict__ bias, int relu,
    const float* __restrict__ a_src, const float* __restrict__ a_dst,
    float* __restrict__ s_out, float* __restrict__ t_out)
{
    constexpr int BM = 128, BK = 16, TN = BN / 16, NG = BN / 64;
    constexpr int ASZ = BM * BK, BSZ = BK * BN;
    extern __shared__ float smdyn[];
    float* Asb = smdyn;                       // 3 stages of A
    float* Bsb = smdyn + 3 * ASZ;             // 3 stages of B
    float* sh_att = smdyn + 3 * (ASZ + BSZ);  // 2*BN

    int tid = threadIdx.x;
    int tx = tid & 15, ty = tid >> 4;
    int blockRow = blockIdx.x * BM;

    if (a_src) {
        if (tid < BN) sh_att[tid] = a_src[tid];
        else if (tid < 2 * BN) sh_att[tid] = a_dst[tid - BN];
    }

    ull acc[8][TN / 2];
#pragma unroll
    for (int i = 0; i < 8; i++)
#pragma unroll
        for (int j = 0; j < TN / 2; j++) acc[i][j] = 0ull;

    int nch = K / BK;

    auto loadA = [&](int c, int st) {
        int k0 = c * BK;
        float* dst = Asb + st * ASZ;
#pragma unroll
        for (int l = 0; l < 2; l++) {
            int f = tid + l * 256;
            int row = f >> 2, q = f & 3;
            int gr = blockRow + row;
            if (gr >= M) gr = M - 1;
            cpa16(smem_u32(dst + row * BK + q * 4), &A[(size_t)gr * K + k0 + q * 4]);
        }
    };
    auto loadB = [&](int c, int st) {
        int k0 = c * BK;
        float* dst = Bsb + st * BSZ;
        constexpr int CH = BK * BN / 4;
#pragma unroll
        for (int l = 0; l < CH / 256; l++) {
            int f = tid + l * 256;
            int kr = f / (BN / 4), q = f % (BN / 4);
            cpa16(smem_u32(dst + kr * BN + q * 4), &B[(size_t)(k0 + kr) * BN + q * 4]);
        }
    };

    // prologue: prefetch chunks 0 and 1 (two commit groups, possibly 2nd empty)
    loadA(0, 0);
    loadB(0, 0);
    asm volatile("cp.async.commit_group;");
    if (nch > 1) {
        loadA(1, 1);
        loadB(1, 1);
    }
    asm volatile("cp.async.commit_group;");

    for (int c = 0; c < nch; c++) {
        int st = c % 3;
        asm volatile("cp.async.wait_group 1;");   // chunk c resident; c+1 may be in flight
        __syncthreads();                           // single barrier per chunk
        if (c + 2 < nch) {
            int sn = (c + 2) % 3;                  // == (c-1)%3: freed by the barrier above
            loadA(c + 2, sn);
            loadB(c + 2, sn);
        }
        asm volatile("cp.async.commit_group;");    // always commit (keeps wait arithmetic fixed)

        const float* Ab = Asb + st * ASZ;
        const float* Bb = Bsb + st * BSZ;
#pragma unroll
        for (int k4 = 0; k4 < BK; k4 += 4) {
            float4 a4[8];
#pragma unroll
            for (int i = 0; i < 8; i++)
                a4[i] = *reinterpret_cast<const float4*>(&Ab[(ty * 8 + i) * BK + k4]);
#pragma unroll
            for (int kk = 0; kk < 4; kk++) {
                ull b2[TN / 2];
#pragma unroll
                for (int g = 0; g < NG; g++) {
                    F4U bu;
                    bu.f = *reinterpret_cast<const float4*>(&Bb[(k4 + kk) * BN + g * 64 + tx * 4]);
                    b2[g * 2 + 0] = bu.u[0];
                    b2[g * 2 + 1] = bu.u[1];
                }
#pragma unroll
                for (int i = 0; i < 8; i++) {
                    float av = (kk == 0) ? a4[i].x : (kk == 1) ? a4[i].y : (kk == 2) ? a4[i].z : a4[i].w;
                    ull a2 = splat2(av);
#pragma unroll
                    for (int j = 0; j < TN / 2; j++) fma2(acc[i][j], a2, b2[j]);
                }
            }
        }
    }

    // ---- per-row epilogue ----
#pragma unroll
    for (int i = 0; i < 8; i++) {
        int r = blockRow + ty * 8 + i;
        float af[TN];
#pragma unroll
        for (int j = 0; j < TN / 2; j++) upk2(acc[i][j], af[2 * j], af[2 * j + 1]);

        if (s_out) {
            if (BN == 128) {
                float ps0 = 0.f, pt0 = 0.f, ps1 = 0.f, pt1 = 0.f;
#pragma unroll
                for (int j = 0; j < 4; j++) {
                    int c0 = tx * 4 + j, c1 = 64 + tx * 4 + j;
                    ps0 += af[j] * sh_att[c0];
                    pt0 += af[j] * sh_att[BN + c0];
                    ps1 += af[4 + j] * sh_att[c1];
                    pt1 += af[4 + j] * sh_att[BN + c1];
                }
#pragma unroll
                for (int off = 8; off; off >>= 1) {
                    ps0 += __shfl_xor_sync(0xFFFFFFFFu, ps0, off);
                    pt0 += __shfl_xor_sync(0xFFFFFFFFu, pt0, off);
                    ps1 += __shfl_xor_sync(0xFFFFFFFFu, ps1, off);
                    pt1 += __shfl_xor_sync(0xFFFFFFFFu, pt1, off);
                }
                if (tx == 0 && r < M) {
                    s_out[r * 2 + 0] = ps0;
                    s_out[r * 2 + 1] = ps1;
                    t_out[r * 2 + 0] = pt0;
                    t_out[r * 2 + 1] = pt1;
                }
            } else {
                float ps = 0.f, pt = 0.f;
#pragma unroll
                for (int j = 0; j < 4; j++) {
                    int col = tx * 4 + j;
                    ps += af[j] * sh_att[col];
                    pt += af[j] * sh_att[BN + col];
                }
#pragma unroll
                for (int off = 8; off; off >>= 1) {
                    ps += __shfl_xor_sync(0xFFFFFFFFu, ps, off);
                    pt += __shfl_xor_sync(0xFFFFFFFFu, pt, off);
                }
                if (tx == 0 && r < M) {
                    s_out[r] = ps;
                    t_out[r] = pt;
                }
            }
        }

        if (r < M) {
#pragma unroll
            for (int g = 0; g < NG; g++) {
                int col = g * 64 + tx * 4;
                float4 v;
                v.x = af[g * 4 + 0];
                v.y = af[g * 4 + 1];
                v.z = af[g * 4 + 2];
                v.w = af[g * 4 + 3];
                if (bias) {
                    v.x += bias[col + 0]; v.y += bias[col + 1];
                    v.z += bias[col + 2]; v.w += bias[col + 3];
                }
                if (relu) {
                    v.x = fmaxf(v.x, 0.f); v.y = fmaxf(v.y, 0.f);
                    v.z = fmaxf(v.z, 0.f); v.w = fmaxf(v.w, 0.f);
                }
                if (C2) {
                    float* dst = (g == 0) ? C : C2;
                    *reinterpret_cast<float4*>(&dst[(size_t)r * 64 + tx * 4]) = v;
                } else {
                    *reinterpret_cast<float4*>(&C[(size_t)r * BN + col]) = v;
                }
            }
        }
    }
}

// ---------------- GAT aggregation: one WARP per dst node (R15 version) --------
template <int H, bool RELU>
__global__ void __launch_bounds__(256) k_aggw(const float* __restrict__ hin,
                                              const float* __restrict__ s,
                                              const float* __restrict__ t,
                                              const int* __restrict__ rowptr,
                                              const int* __restrict__ col,
                                              const float* __restrict__ bias,
                                              float* __restrict__ out, int n) {
    int node = (blockIdx.x * 256 + threadIdx.x) >> 5;
    if (node >= n) return;
    int lane = threadIdx.x & 31;
    int start = rowptr[node];
    int deg = rowptr[node + 1] - start;

    float tn[H];
#pragma unroll
    for (int h = 0; h < H; h++) tn[h] = t[node * H + h];

    float4 acc = make_float4(0.f, 0.f, 0.f, 0.f);

    auto gather = [&](int src, float al0, float al1, int cnt) {
        int e2 = 0;
        for (; e2 + 4 <= cnt; e2 += 4) {
            int sb0 = __shfl_sync(0xFFFFFFFFu, src, e2 + 0);
            int sb1 = __shfl_sync(0xFFFFFFFFu, src, e2 + 1);
            int sb2 = __shfl_sync(0xFFFFFFFFu, src, e2 + 2);
            int sb3 = __shfl_sync(0xFFFFFFFFu, src, e2 + 3);
            float p0 = __shfl_sync(0xFFFFFFFFu, al0, e2 + 0);
            float p1 = __shfl_sync(0xFFFFFFFFu, al0, e2 + 1);
            float p2 = __shfl_sync(0xFFFFFFFFu, al0, e2 + 2);
            float p3 = __shfl_sync(0xFFFFFFFFu, al0, e2 + 3);
            if (H == 2) {
                float q0 = __shfl_sync(0xFFFFFFFFu, al1, e2 + 0);
                float q1 = __shfl_sync(0xFFFFFFFFu, al1, e2 + 1);
                float q2 = __shfl_sync(0xFFFFFFFFu, al1, e2 + 2);
                float q3 = __shfl_sync(0xFFFFFFFFu, al1, e2 + 3);
                float a0 = (lane < 16) ? p0 : q0;
                float a1 = (lane < 16) ? p1 : q1;
                float a2 = (lane < 16) ? p2 : q2;
                float a3 = (lane < 16) ? p3 : q3;
                float4 v0 = *reinterpret_cast<const float4*>(hin + (size_t)sb0 * 128 + lane * 4);
                float4 v1 = *reinterpret_cast<const float4*>(hin + (size_t)sb1 * 128 + lane * 4);
                float4 v2 = *reinterpret_cast<const float4*>(hin + (size_t)sb2 * 128 + lane * 4);
                float4 v3 = *reinterpret_cast<const float4*>(hin + (size_t)sb3 * 128 + lane * 4);
                acc.x = fmaf(a0, v0.x, acc.x); acc.y = fmaf(a0, v0.y, acc.y);
                acc.z = fmaf(a0, v0.z, acc.z); acc.w = fmaf(a0, v0.w, acc.w);
                acc.x = fmaf(a1, v1.x, acc.x); acc.y = fmaf(a1, v1.y, acc.y);
                acc.z = fmaf(a1, v1.z, acc.z); acc.w = fmaf(a1, v1.w, acc.w);
                acc.x = fmaf(a2, v2.x, acc.x); acc.y = fmaf(a2, v2.y, acc.y);
                acc.z = fmaf(a2, v2.z, acc.z); acc.w = fmaf(a2, v2.w, acc.w);
                acc.x = fmaf(a3, v3.x, acc.x); acc.y = fmaf(a3, v3.y, acc.y);
                acc.z = fmaf(a3, v3.z, acc.z); acc.w = fmaf(a3, v3.w, acc.w);
            } else {
                float2 v0 = *reinterpret_cast<const float2*>(hin + (size_t)sb0 * 64 + lane * 2);
                float2 v1 = *reinterpret_cast<const float2*>(hin + (size_t)sb1 * 64 + lane * 2);
                float2 v2 = *reinterpret_cast<const float2*>(hin + (size_t)sb2 * 64 + lane * 2);
                float2 v3 = *reinterpret_cast<const float2*>(hin + (size_t)sb3 * 64 + lane * 2);
                acc.x = fmaf(p0, v0.x, acc.x); acc.y = fmaf(p0, v0.y, acc.y);
                acc.x = fmaf(p1, v1.x, acc.x); acc.y = fmaf(p1, v1.y, acc.y);
                acc.x = fmaf(p2, v2.x, acc.x); acc.y = fmaf(p2, v2.y, acc.y);
                acc.x = fmaf(p3, v3.x, acc.x); acc.y = fmaf(p3, v3.y, acc.y);
            }
        }
        for (; e2 < cnt; e2++) {
            int sb = __shfl_sync(0xFFFFFFFFu, src, e2);
            float p = __shfl_sync(0xFFFFFFFFu, al0, e2);
            if (H == 2) {
                float q = __shfl_sync(0xFFFFFFFFu, al1, e2);
                float a = (lane < 16) ? p : q;
                float4 hv = *reinterpret_cast<const float4*>(hin + (size_t)sb * 128 + lane * 4);
                acc.x = fmaf(a, hv.x, acc.x); acc.y = fmaf(a, hv.y, acc.y);
                acc.z = fmaf(a, hv.z, acc.z); acc.w = fmaf(a, hv.w, acc.w);
            } else {
                float2 hv = *reinterpret_cast<const float2*>(hin + (size_t)sb * 64 + lane * 2);
                acc.x = fmaf(p, hv.x, acc.x);
                acc.y = fmaf(p, hv.y, acc.y);
            }
        }
    };

    if (deg <= 32) {
        int src = 0;
        float e0 = -1e30f, e1 = -1e30f;
        bool act = lane < deg;
        if (act) {
            src = col[start + lane];
            if (H == 2) {
                float2 sv = *reinterpret_cast<const float2*>(&s[src * 2]);
                e0 = sv.x + tn[0];
                e0 = e0 > 0.f ? e0 : NEG_SLOPE * e0;
                e1 = sv.y + tn[1];
                e1 = e1 > 0.f ? e1 : NEG_SLOPE * e1;
            } else {
                e0 = s[src] + tn[0];
                e0 = e0 > 0.f ? e0 : NEG_SLOPE * e0;
            }
        }
        float m0 = e0, m1 = e1;
#pragma unroll
        for (int off = 16; off; off >>= 1) {
            m0 = fmaxf(m0, __shfl_xor_sync(0xFFFFFFFFu, m0, off));
            if (H == 2) m1 = fmaxf(m1, __shfl_xor_sync(0xFFFFFFFFu, m1, off));
        }
        float x0 = act ? __expf(e0 - m0) : 0.f;
        float x1 = (H == 2 && act) ? __expf(e1 - m1) : 0.f;
        float s0 = x0, s1 = x1;
#pragma unroll
        for (int off = 16; off; off >>= 1) {
            s0 += __shfl_xor_sync(0xFFFFFFFFu, s0, off);
            if (H == 2) s1 += __shfl_xor_sync(0xFFFFFFFFu, s1, off);
        }
        float al0 = x0 / (s0 + 1e-16f);
        float al1 = (H == 2) ? x1 / (s1 + 1e-16f) : al0;
        gather(src, al0, al1, deg);
    } else {
        float m[H], sm[H];
#pragma unroll
        for (int h = 0; h < H; h++) { m[h] = -1e30f; sm[h] = 0.f; }
        for (int k = lane; k < deg; k += 32) {
            int src = col[start + k];
            float e[H];
            if (H == 2) {
                float2 sv = *reinterpret_cast<const float2*>(&s[src * 2]);
                e[0] = sv.x + tn[0];
                e[1] = sv.y + tn[1];
            } else {
                e[0] = s[src] + tn[0];
            }
#pragma unroll
            for (int h = 0; h < H; h++) {
                float eh = e[h];
                eh = eh > 0.f ? eh : NEG_SLOPE * eh;
                float old = m[h];
                float nm = fmaxf(old, eh);
                sm[h] = sm[h] * __expf(old - nm) + __expf(eh - nm);
                m[h] = nm;
            }
        }
        float inv[H];
#pragma unroll
        for (int h = 0; h < H; h++) {
#pragma unroll
            for (int off = 16; off; off >>= 1) {
                float mo = __shfl_xor_sync(0xFFFFFFFFu, m[h], off);
                float so = __shfl_xor_sync(0xFFFFFFFFu, sm[h], off);
                float nm = fmaxf(m[h], mo);
                sm[h] = sm[h] * __expf(m[h] - nm) + so * __expf(mo - nm);
                m[h] = nm;
            }
            inv[h] = 1.f / (sm[h] + 1e-16f);
        }

        for (int base = 0; base < deg; base += 32) {
            int k = base + lane;
            int src = 0;
            float al0 = 0.f, al1 = 0.f;
            if (k < deg) {
                src = col[start + k];
                if (H == 2) {
                    float2 sv = *reinterpret_cast<const float2*>(&s[src * 2]);
                    float e0 = sv.x + tn[0];
                    e0 = e0 > 0.f ? e0 : NEG_SLOPE * e0;
                    al0 = __expf(e0 - m[0]) * inv[0];
                    float e1 = sv.y + tn[1];
                    e1 = e1 > 0.f ? e1 : NEG_SLOPE * e1;
                    al1 = __expf(e1 - m[1]) * inv[1];
                } else {
                    float e = s[src] + tn[0];
                    e = e > 0.f ? e : NEG_SLOPE * e;
                    al0 = __expf(e - m[0]) * inv[0];
                }
            }
            gather(src, al0, al1, min(32, deg - base));
        }
    }

    if (H == 2) {
        float4 bv = *reinterpret_cast<const float4*>(bias + lane * 4);
        float4 v;
        v.x = acc.x + bv.x;
        v.y = acc.y + bv.y;
        v.z = acc.z + bv.z;
        v.w = acc.w + bv.w;
        if (RELU) {
            v.x = fmaxf(v.x, 0.f); v.y = fmaxf(v.y, 0.f);
            v.z = fmaxf(v.z, 0.f); v.w = fmaxf(v.w, 0.f);
        }
        *reinterpret_cast<float4*>(out + (size_t)node * 128 + lane * 4) = v;
    } else {
        float2 bv = *reinterpret_cast<const float2*>(bias + lane * 2);
        float2 v;
        v.x = acc.x + bv.x;
        v.y = acc.y + bv.y;
        if (RELU) {
            v.x = fmaxf(v.x, 0.f);
            v.y = fmaxf(v.y, 0.f);
        }
        *reinterpret_cast<float2*>(out + (size_t)node * 64 + lane * 2) = v;
    }
}

// ---------------- host launch ----------------
extern "C" void kernel_launch(void* const* d_in, const int* in_sizes, int n_in,
                              void* d_out, int out_size) {
    const float* x     = (const float*)d_in[0];
    const int*   ei    = (const int*)d_in[1];
    const float* W0    = (const float*)d_in[2];
    const float* as0   = (const float*)d_in[3];
    const float* ad0   = (const float*)d_in[4];
    const float* b0    = (const float*)d_in[5];
    const float* W1    = (const float*)d_in[6];
    const float* as1   = (const float*)d_in[7];
    const float* ad1   = (const float*)d_in[8];
    const float* b1    = (const float*)d_in[9];
    const float* W2    = (const float*)d_in[10];
    const float* as2   = (const float*)d_in[11];
    const float* ad2   = (const float*)d_in[12];
    const float* b2    = (const float*)d_in[13];
    const float* Wv    = (const float*)d_in[14];
    const float* bv    = (const float*)d_in[15];
    const float* Wt    = (const float*)d_in[16];
    const float* bt    = (const float*)d_in[17];

    int N = in_sizes[0] / 512;
    int E = in_sizes[1] / 2;

    float* out = (float*)d_out;
    float* h_out = out;
    float* vis = out + (size_t)N * 64;
    float* txt = out + (size_t)N * 64 * 2;

    float *h0, *h1, *sA, *tA, *Wcat, *bcat;
    int *deg, *rowptr, *cursor, *colA, *bsum, *bexc;
    cudaGetSymbolAddress((void**)&h0, g_h0);
    cudaGetSymbolAddress((void**)&h1, g_h1);
    cudaGetSymbolAddress((void**)&sA, g_s);
    cudaGetSymbolAddress((void**)&tA, g_t);
    cudaGetSymbolAddress((void**)&deg, g_deg);
    cudaGetSymbolAddress((void**)&rowptr, g_rowptr);
    cudaGetSymbolAddress((void**)&cursor, g_cursor);
    cudaGetSymbolAddress((void**)&colA, g_col);
    cudaGetSymbolAddress((void**)&bsum, g_bsum);
    cudaGetSymbolAddress((void**)&bexc, g_bexc);
    cudaGetSymbolAddress((void**)&Wcat, g_Wcat);
    cudaGetSymbolAddress((void**)&bcat, g_bcat);

    // dynamic smem: 3 stages of (A + B) + attention vectors
    const int SM128 = 3 * (128 * 16 + 16 * 128) * 4 + 2 * 128 * 4;  // 50176 B
    const int SM64  = 3 * (128 * 16 + 16 * 64) * 4 + 2 * 64 * 4;    // 37376 B
    cudaFuncSetAttribute(k_gemm<128>, cudaFuncAttributeMaxDynamicSharedMemorySize, SM128);
    cudaFuncSetAttribute(k_gemm<64>, cudaFuncAttributeMaxDynamicSharedMemorySize, SM64);

    static cudaStream_t s2 = nullptr;
    static cudaEvent_t evFork = nullptr, evJoin = nullptr;
    if (!s2) {
        cudaStreamCreateWithFlags(&s2, cudaStreamNonBlocking);
        cudaEventCreateWithFlags(&evFork, cudaEventDisableTiming);
        cudaEventCreateWithFlags(&evJoin, cudaEventDisableTiming);
    }

    int nb = (N + 255) / 256;
    int gblk = (N + 127) / 128;
    int wgrid = (N * 32 + 255) / 256;

    // ---- fork: 3 CSR kernels first (launches 1-3), GEMM0 4th (ncu slot) ----
    cudaEventRecord(evFork, 0);
    cudaStreamWaitEvent(s2, evFork, 0);
    k_init_deg<<<nb, 256, 0, s2>>>(deg, N);
    k_hist<<<(E + 255) / 256, 256, 0, s2>>>(ei, E, deg);
    k_blocksums<<<nb, 256, 0, s2>>>(deg, bsum, N);

    k_gemm<128><<<gblk, 256, SM128>>>(x, W0, h0, nullptr, N, 512, nullptr, 0,
                                      as0, ad0, sA, tA);

    k_scan_top<<<1, 256, 0, s2>>>(bsum, bexc, nb);
    k_scan_apply<<<nb, 256, 0, s2>>>(deg, bexc, rowptr, cursor, colA, N);
    k_scatter<<<(E + 255) / 256, 256, 0, s2>>>(ei, E, cursor, colA);
    k_prep<<<(64 * 128 + 255) / 256, 256, 0, s2>>>(Wv, bv, Wt, bt, Wcat, bcat);
    cudaEventRecord(evJoin, s2);

    // ---- join ----
    cudaStreamWaitEvent(0, evJoin, 0);

    // ---- layer 0 aggregation ----
    k_aggw<2, true><<<wgrid, 256>>>(h0, sA, tA, rowptr, colA, b0, h1, N);

    // ---- layer 1 ----
    k_gemm<128><<<gblk, 256, SM128>>>(h1, W1, h0, nullptr, N, 128, nullptr, 0,
                                      as1, ad1, sA, tA);
    k_aggw<2, true><<<wgrid, 256>>>(h0, sA, tA, rowptr, colA, b1, h1, N);

    // ---- layer 2 (heads=1, no relu) ----
    k_gemm<64><<<gblk, 256, SM64>>>(h1, W2, h0, nullptr, N, 128, nullptr, 0,
                                    as2, ad2, sA, tA);
    k_aggw<1, false><<<wgrid, 256>>>(h0, sA, tA, rowptr, colA, b2, h_out, N);

    // ---- MLP heads: one combined GEMM with split store ----
    k_gemm<128><<<gblk, 256, SM128>>>(h_out, Wcat, vis, txt, N, 64, bcat, 1,
                                      nullptr, nullptr, nullptr, nullptr);
}

// round 17
// speedup vs baseline: 1.1502x; 1.0195x over previous
#include <cuda_runtime.h>
#include <cstdint>

#define NNODES 50000
#define NEDGES 800000
#define TOTEDGES (NEDGES + NNODES)
#define NEG_SLOPE 0.2f

// ---------------- scratch (allocation-free: device globals) ----------------
__device__ float g_h0[(size_t)NNODES * 128];
__device__ float g_h1[(size_t)NNODES * 128];
__device__ float g_s[NNODES * 2];
__device__ float g_t[NNODES * 2];
__device__ int   g_deg[NNODES];
__device__ int   g_rowptr[NNODES + 1];
__device__ int   g_cursor[NNODES];
__device__ int   g_col[TOTEDGES];
__device__ int   g_bsum[256];
__device__ int   g_bexc[256];
__device__ float g_Wcat[64 * 128];
__device__ float g_bcat[128];

// ---------------- helpers ----------------
__device__ __forceinline__ uint32_t smem_u32(const void* p) {
    return (uint32_t)__cvta_generic_to_shared(p);
}
typedef unsigned long long ull;
union F4U { float4 f; ull u[2]; };
__device__ __forceinline__ ull splat2(float x) {
    ull r;
    asm("mov.b64 %0, {%1, %1};" : "=l"(r) : "f"(x));
    return r;
}
__device__ __forceinline__ void fma2(ull& d, ull a, ull b) {
    asm("fma.rn.f32x2 %0, %1, %2, %3;" : "=l"(d) : "l"(a), "l"(b), "l"(d));
}
__device__ __forceinline__ void upk2(ull v, float& lo, float& hi) {
    asm("mov.b64 {%0, %1}, %2;" : "=f"(lo), "=f"(hi) : "l"(v));
}
__device__ __forceinline__ void cpa16(uint32_t dst, const void* src) {
    asm volatile("cp.async.cg.shared.global [%0], [%1], 16;" :: "r"(dst), "l"(src));
}

// ---------------- CSR build ----------------
__global__ void k_init_deg(int* __restrict__ deg, int n) {
    int i = blockIdx.x * blockDim.x + threadIdx.x;
    if (i < n) deg[i] = 1;
}
__global__ void k_hist(const int* __restrict__ ei, int e, int* __restrict__ deg) {
    int i = blockIdx.x * blockDim.x + threadIdx.x;
    if (i < e) atomicAdd(&deg[ei[e + i]], 1);
}
__global__ void k_blocksums(const int* __restrict__ deg, int* __restrict__ bsum, int n) {
    __shared__ int wred[8];
    int i = blockIdx.x * 256 + threadIdx.x;
    int v = (i < n) ? deg[i] : 0;
    int lane = threadIdx.x & 31, w = threadIdx.x >> 5;
#pragma unroll
    for (int off = 16; off; off >>= 1) v += __shfl_xor_sync(0xFFFFFFFFu, v, off);
    if (lane == 0) wred[w] = v;
    __syncthreads();
    if (threadIdx.x == 0) {
        int s = 0;
#pragma unroll
        for (int k = 0; k < 8; k++) s += wred[k];
        bsum[blockIdx.x] = s;
    }
}
__global__ void k_scan_top(const int* __restrict__ bsum, int* __restrict__ bexc, int nb) {
    __shared__ int wred[8];
    int tid = threadIdx.x, lane = tid & 31, w = tid >> 5;
    int v = (tid < nb) ? bsum[tid] : 0;
    int x = v;
#pragma unroll
    for (int off = 1; off < 32; off <<= 1) {
        int y = __shfl_up_sync(0xFFFFFFFFu, x, off);
        if (lane >= off) x += y;
    }
    if (lane == 31) wred[w] = x;
    __syncthreads();
    if (w == 0) {
        int sv = (lane < 8) ? wred[lane] : 0;
#pragma unroll
        for (int off = 1; off < 8; off <<= 1) {
            int y = __shfl_up_sync(0xFFFFFFFFu, sv, off);
            if (lane >= off) sv += y;
        }
        if (lane < 8) wred[lane] = sv;
    }
    __syncthreads();
    int woff = (w > 0) ? wred[w - 1] : 0;
    if (tid < nb) bexc[tid] = x + woff - v;
}
__global__ void k_scan_apply(const int* __restrict__ deg, const int* __restrict__ bexc,
                             int* __restrict__ rowptr, int* __restrict__ cursor,
                             int* __restrict__ col, int n) {
    __shared__ int wred[8];
    int i = blockIdx.x * 256 + threadIdx.x;
    int tid = threadIdx.x, lane = tid & 31, w = tid >> 5;
    int v = (i < n) ? deg[i] : 0;
    int x = v;
#pragma unroll
    for (int off = 1; off < 32; off <<= 1) {
        int y = __shfl_up_sync(0xFFFFFFFFu, x, off);
        if (lane >= off) x += y;
    }
    if (lane == 31) wred[w] = x;
    __syncthreads();
    if (w == 0) {
        int sv = (lane < 8) ? wred[lane] : 0;
#pragma unroll
        for (int off = 1; off < 8; off <<= 1) {
            int y = __shfl_up_sync(0xFFFFFFFFu, sv, off);
            if (lane >= off) sv += y;
        }
        if (lane < 8) wred[lane] = sv;
    }
    __syncthreads();
    int woff = (w > 0) ? wred[w - 1] : 0;
    if (i < n) {
        int incl = x + woff + bexc[blockIdx.x];
        rowptr[i + 1] = incl;
        int p = incl - v;
        col[p] = i;
        cursor[i] = p + 1;
        if (i == 0) rowptr[0] = 0;
    }
}
__global__ void k_scatter(const int* __restrict__ ei, int e, int* __restrict__ cursor,
                          int* __restrict__ col) {
    int i = blockIdx.x * blockDim.x + threadIdx.x;
    if (i < e) {
        int s = ei[i];
        int d = ei[e + i];
        int p = atomicAdd(&cursor[d], 1);
        col[p] = s;
    }
}

// ---------------- Wcat prep ----------------
__global__ void k_prep(const float* __restrict__ Wv, const float* __restrict__ bv,
                       const float* __restrict__ Wt, const float* __restrict__ bt,
                       float* __restrict__ Wcat, float* __restrict__ bcat) {
    int i = blockIdx.x * blockDim.x + threadIdx.x;
    if (i < 64 * 128) {
        int k = i >> 7, n = i & 127;
        Wcat[i] = (n < 64) ? Wv[k * 64 + n] : Wt[k * 64 + (n - 64)];
    }
    if (i < 128) bcat[i] = (i < 64) ? bv[i] : bt[i - 64];
}

// ---------------- f32x2 GEMM: BK=32, 3-stage cp.async pipeline, 1 sync/chunk ---
template <int BN>
__global__ void __launch_bounds__(256, 2) k_gemm(
    const float* __restrict__ A, const float* __restrict__ B,
    float* __restrict__ C, float* __restrict__ C2, int M, int K,
    const float* __restrict__ bias, int relu,
    const float* __restrict__ a_src, const float* __restrict__ a_dst,
    float* __restrict__ s_out, float* __restrict__ t_out)
{
    constexpr int BM = 128, BK = 32, TN = BN / 16, NG = BN / 64;
    constexpr int ASZ = BM * BK, BSZ = BK * BN;
    extern __shared__ float smdyn[];
    float* Asb = smdyn;                       // 3 stages of A
    float* Bsb = smdyn + 3 * ASZ;             // 3 stages of B
    float* sh_att = smdyn + 3 * (ASZ + BSZ);  // 2*BN

    int tid = threadIdx.x;
    int tx = tid & 15, ty = tid >> 4;
    int blockRow = blockIdx.x * BM;

    if (a_src) {
        if (tid < BN) sh_att[tid] = a_src[tid];
        else if (tid < 2 * BN) sh_att[tid] = a_dst[tid - BN];
    }

    ull acc[8][TN / 2];
#pragma unroll
    for (int i = 0; i < 8; i++)
#pragma unroll
        for (int j = 0; j < TN / 2; j++) acc[i][j] = 0ull;

    int nch = K / BK;

    auto loadA = [&](int c, int st) {
        int k0 = c * BK;
        float* dst = Asb + st * ASZ;
        // 128 rows x 8 float4 = 1024 float4 over 256 threads
#pragma unroll
        for (int l = 0; l < 4; l++) {
            int f = tid + l * 256;
            int row = f >> 3, q = f & 7;
            int gr = blockRow + row;
            if (gr >= M) gr = M - 1;
            cpa16(smem_u32(dst + row * BK + q * 4), &A[(size_t)gr * K + k0 + q * 4]);
        }
    };
    auto loadB = [&](int c, int st) {
        int k0 = c * BK;
        float* dst = Bsb + st * BSZ;
        constexpr int CH = BK * BN / 4;   // 1024 (BN=128) or 512 (BN=64)
#pragma unroll
        for (int l = 0; l < CH / 256; l++) {
            int f = tid + l * 256;
            int kr = f / (BN / 4), q = f % (BN / 4);
            cpa16(smem_u32(dst + kr * BN + q * 4), &B[(size_t)(k0 + kr) * BN + q * 4]);
        }
    };

    // prologue: prefetch chunks 0 and 1
    loadA(0, 0);
    loadB(0, 0);
    asm volatile("cp.async.commit_group;");
    if (nch > 1) {
        loadA(1, 1);
        loadB(1, 1);
    }
    asm volatile("cp.async.commit_group;");

    for (int c = 0; c < nch; c++) {
        int st = c % 3;
        asm volatile("cp.async.wait_group 1;");
        __syncthreads();
        if (c + 2 < nch) {
            int sn = (c + 2) % 3;
            loadA(c + 2, sn);
            loadB(c + 2, sn);
        }
        asm volatile("cp.async.commit_group;");

        const float* Ab = Asb + st * ASZ;
        const float* Bb = Bsb + st * BSZ;
#pragma unroll
        for (int k4 = 0; k4 < BK; k4 += 4) {
            float4 a4[8];
#pragma unroll
            for (int i = 0; i < 8; i++)
                a4[i] = *reinterpret_cast<const float4*>(&Ab[(ty * 8 + i) * BK + k4]);
#pragma unroll
            for (int kk = 0; kk < 4; kk++) {
                ull b2[TN / 2];
#pragma unroll
                for (int g = 0; g < NG; g++) {
                    F4U bu;
                    bu.f = *reinterpret_cast<const float4*>(&Bb[(k4 + kk) * BN + g * 64 + tx * 4]);
                    b2[g * 2 + 0] = bu.u[0];
                    b2[g * 2 + 1] = bu.u[1];
                }
#pragma unroll
                for (int i = 0; i < 8; i++) {
                    float av = (kk == 0) ? a4[i].x : (kk == 1) ? a4[i].y : (kk == 2) ? a4[i].z : a4[i].w;
                    ull a2 = splat2(av);
#pragma unroll
                    for (int j = 0; j < TN / 2; j++) fma2(acc[i][j], a2, b2[j]);
                }
            }
        }
    }

    // ---- per-row epilogue ----
#pragma unroll
    for (int i = 0; i < 8; i++) {
        int r = blockRow + ty * 8 + i;
        float af[TN];
#pragma unroll
        for (int j = 0; j < TN / 2; j++) upk2(acc[i][j], af[2 * j], af[2 * j + 1]);

        if (s_out) {
            if (BN == 128) {
                float ps0 = 0.f, pt0 = 0.f, ps1 = 0.f, pt1 = 0.f;
#pragma unroll
                for (int j = 0; j < 4; j++) {
                    int c0 = tx * 4 + j, c1 = 64 + tx * 4 + j;
                    ps0 += af[j] * sh_att[c0];
                    pt0 += af[j] * sh_att[BN + c0];
                    ps1 += af[4 + j] * sh_att[c1];
                    pt1 += af[4 + j] * sh_att[BN + c1];
                }
#pragma unroll
                for (int off = 8; off; off >>= 1) {
                    ps0 += __shfl_xor_sync(0xFFFFFFFFu, ps0, off);
                    pt0 += __shfl_xor_sync(0xFFFFFFFFu, pt0, off);
                    ps1 += __shfl_xor_sync(0xFFFFFFFFu, ps1, off);
                    pt1 += __shfl_xor_sync(0xFFFFFFFFu, pt1, off);
                }
                if (tx == 0 && r < M) {
                    s_out[r * 2 + 0] = ps0;
                    s_out[r * 2 + 1] = ps1;
                    t_out[r * 2 + 0] = pt0;
                    t_out[r * 2 + 1] = pt1;
                }
            } else {
                float ps = 0.f, pt = 0.f;
#pragma unroll
                for (int j = 0; j < 4; j++) {
                    int col = tx * 4 + j;
                    ps += af[j] * sh_att[col];
                    pt += af[j] * sh_att[BN + col];
                }
#pragma unroll
                for (int off = 8; off; off >>= 1) {
                    ps += __shfl_xor_sync(0xFFFFFFFFu, ps, off);
                    pt += __shfl_xor_sync(0xFFFFFFFFu, pt, off);
                }
                if (tx == 0 && r < M) {
                    s_out[r] = ps;
                    t_out[r] = pt;
                }
            }
        }

        if (r < M) {
#pragma unroll
            for (int g = 0; g < NG; g++) {
                int col = g * 64 + tx * 4;
                float4 v;
                v.x = af[g * 4 + 0];
                v.y = af[g * 4 + 1];
                v.z = af[g * 4 + 2];
                v.w = af[g * 4 + 3];
                if (bias) {
                    v.x += bias[col + 0]; v.y += bias[col + 1];
                    v.z += bias[col + 2]; v.w += bias[col + 3];
                }
                if (relu) {
                    v.x = fmaxf(v.x, 0.f); v.y = fmaxf(v.y, 0.f);
                    v.z = fmaxf(v.z, 0.f); v.w = fmaxf(v.w, 0.f);
                }
                if (C2) {
                    float* dst = (g == 0) ? C : C2;
                    *reinterpret_cast<float4*>(&dst[(size_t)r * 64 + tx * 4]) = v;
                } else {
                    *reinterpret_cast<float4*>(&C[(size_t)r * BN + col]) = v;
                }
            }
        }
    }
}

// ---------------- GAT aggregation: one WARP per dst node (R15 version) --------
template <int H, bool RELU>
__global__ void __launch_bounds__(256) k_aggw(const float* __restrict__ hin,
                                              const float* __restrict__ s,
                                              const float* __restrict__ t,
                                              const int* __restrict__ rowptr,
                                              const int* __restrict__ col,
                                              const float* __restrict__ bias,
                                              float* __restrict__ out, int n) {
    int node = (blockIdx.x * 256 + threadIdx.x) >> 5;
    if (node >= n) return;
    int lane = threadIdx.x & 31;
    int start = rowptr[node];
    int deg = rowptr[node + 1] - start;

    float tn[H];
#pragma unroll
    for (int h = 0; h < H; h++) tn[h] = t[node * H + h];

    float4 acc = make_float4(0.f, 0.f, 0.f, 0.f);

    auto gather = [&](int src, float al0, float al1, int cnt) {
        int e2 = 0;
        for (; e2 + 4 <= cnt; e2 += 4) {
            int sb0 = __shfl_sync(0xFFFFFFFFu, src, e2 + 0);
            int sb1 = __shfl_sync(0xFFFFFFFFu, src, e2 + 1);
            int sb2 = __shfl_sync(0xFFFFFFFFu, src, e2 + 2);
            int sb3 = __shfl_sync(0xFFFFFFFFu, src, e2 + 3);
            float p0 = __shfl_sync(0xFFFFFFFFu, al0, e2 + 0);
            float p1 = __shfl_sync(0xFFFFFFFFu, al0, e2 + 1);
            float p2 = __shfl_sync(0xFFFFFFFFu, al0, e2 + 2);
            float p3 = __shfl_sync(0xFFFFFFFFu, al0, e2 + 3);
            if (H == 2) {
                float q0 = __shfl_sync(0xFFFFFFFFu, al1, e2 + 0);
                float q1 = __shfl_sync(0xFFFFFFFFu, al1, e2 + 1);
                float q2 = __shfl_sync(0xFFFFFFFFu, al1, e2 + 2);
                float q3 = __shfl_sync(0xFFFFFFFFu, al1, e2 + 3);
                float a0 = (lane < 16) ? p0 : q0;
                float a1 = (lane < 16) ? p1 : q1;
                float a2 = (lane < 16) ? p2 : q2;
                float a3 = (lane < 16) ? p3 : q3;
                float4 v0 = *reinterpret_cast<const float4*>(hin + (size_t)sb0 * 128 + lane * 4);
                float4 v1 = *reinterpret_cast<const float4*>(hin + (size_t)sb1 * 128 + lane * 4);
                float4 v2 = *reinterpret_cast<const float4*>(hin + (size_t)sb2 * 128 + lane * 4);
                float4 v3 = *reinterpret_cast<const float4*>(hin + (size_t)sb3 * 128 + lane * 4);
                acc.x = fmaf(a0, v0.x, acc.x); acc.y = fmaf(a0, v0.y, acc.y);
                acc.z = fmaf(a0, v0.z, acc.z); acc.w = fmaf(a0, v0.w, acc.w);
                acc.x = fmaf(a1, v1.x, acc.x); acc.y = fmaf(a1, v1.y, acc.y);
                acc.z = fmaf(a1, v1.z, acc.z); acc.w = fmaf(a1, v1.w, acc.w);
                acc.x = fmaf(a2, v2.x, acc.x); acc.y = fmaf(a2, v2.y, acc.y);
                acc.z = fmaf(a2, v2.z, acc.z); acc.w = fmaf(a2, v2.w, acc.w);
                acc.x = fmaf(a3, v3.x, acc.x); acc.y = fmaf(a3, v3.y, acc.y);
                acc.z = fmaf(a3, v3.z, acc.z); acc.w = fmaf(a3, v3.w, acc.w);
            } else {
                float2 v0 = *reinterpret_cast<const float2*>(hin + (size_t)sb0 * 64 + lane * 2);
                float2 v1 = *reinterpret_cast<const float2*>(hin + (size_t)sb1 * 64 + lane * 2);
                float2 v2 = *reinterpret_cast<const float2*>(hin + (size_t)sb2 * 64 + lane * 2);
                float2 v3 = *reinterpret_cast<const float2*>(hin + (size_t)sb3 * 64 + lane * 2);
                acc.x = fmaf(p0, v0.x, acc.x); acc.y = fmaf(p0, v0.y, acc.y);
                acc.x = fmaf(p1, v1.x, acc.x); acc.y = fmaf(p1, v1.y, acc.y);
                acc.x = fmaf(p2, v2.x, acc.x); acc.y = fmaf(p2, v2.y, acc.y);
                acc.x = fmaf(p3, v3.x, acc.x); acc.y = fmaf(p3, v3.y, acc.y);
            }
        }
        for (; e2 < cnt; e2++) {
            int sb = __shfl_sync(0xFFFFFFFFu, src, e2);
            float p = __shfl_sync(0xFFFFFFFFu, al0, e2);
            if (H == 2) {
                float q = __shfl_sync(0xFFFFFFFFu, al1, e2);
                float a = (lane < 16) ? p : q;
                float4 hv = *reinterpret_cast<const float4*>(hin + (size_t)sb * 128 + lane * 4);
                acc.x = fmaf(a, hv.x, acc.x); acc.y = fmaf(a, hv.y, acc.y);
                acc.z = fmaf(a, hv.z, acc.z); acc.w = fmaf(a, hv.w, acc.w);
            } else {
                float2 hv = *reinterpret_cast<const float2*>(hin + (size_t)sb * 64 + lane * 2);
                acc.x = fmaf(p, hv.x, acc.x);
                acc.y = fmaf(p, hv.y, acc.y);
            }
        }
    };

    if (deg <= 32) {
        int src = 0;
        float e0 = -1e30f, e1 = -1e30f;
        bool act = lane < deg;
        if (act) {
            src = col[start + lane];
            if (H == 2) {
                float2 sv = *reinterpret_cast<const float2*>(&s[src * 2]);
                e0 = sv.x + tn[0];
                e0 = e0 > 0.f ? e0 : NEG_SLOPE * e0;
                e1 = sv.y + tn[1];
                e1 = e1 > 0.f ? e1 : NEG_SLOPE * e1;
            } else {
                e0 = s[src] + tn[0];
                e0 = e0 > 0.f ? e0 : NEG_SLOPE * e0;
            }
        }
        float m0 = e0, m1 = e1;
#pragma unroll
        for (int off = 16; off; off >>= 1) {
            m0 = fmaxf(m0, __shfl_xor_sync(0xFFFFFFFFu, m0, off));
            if (H == 2) m1 = fmaxf(m1, __shfl_xor_sync(0xFFFFFFFFu, m1, off));
        }
        float x0 = act ? __expf(e0 - m0) : 0.f;
        float x1 = (H == 2 && act) ? __expf(e1 - m1) : 0.f;
        float s0 = x0, s1 = x1;
#pragma unroll
        for (int off = 16; off; off >>= 1) {
            s0 += __shfl_xor_sync(0xFFFFFFFFu, s0, off);
            if (H == 2) s1 += __shfl_xor_sync(0xFFFFFFFFu, s1, off);
        }
        float al0 = x0 / (s0 + 1e-16f);
        float al1 = (H == 2) ? x1 / (s1 + 1e-16f) : al0;
        gather(src, al0, al1, deg);
    } else {
        float m[H], sm[H];
#pragma unroll
        for (int h = 0; h < H; h++) { m[h] = -1e30f; sm[h] = 0.f; }
        for (int k = lane; k < deg; k += 32) {
            int src = col[start + k];
            float e[H];
            if (H == 2) {
                float2 sv = *reinterpret_cast<const float2*>(&s[src * 2]);
                e[0] = sv.x + tn[0];
                e[1] = sv.y + tn[1];
            } else {
                e[0] = s[src] + tn[0];
            }
#pragma unroll
            for (int h = 0; h < H; h++) {
                float eh = e[h];
                eh = eh > 0.f ? eh : NEG_SLOPE * eh;
                float old = m[h];
                float nm = fmaxf(old, eh);
                sm[h] = sm[h] * __expf(old - nm) + __expf(eh - nm);
                m[h] = nm;
            }
        }
        float inv[H];
#pragma unroll
        for (int h = 0; h < H; h++) {
#pragma unroll
            for (int off = 16; off; off >>= 1) {
                float mo = __shfl_xor_sync(0xFFFFFFFFu, m[h], off);
                float so = __shfl_xor_sync(0xFFFFFFFFu, sm[h], off);
                float nm = fmaxf(m[h], mo);
                sm[h] = sm[h] * __expf(m[h] - nm) + so * __expf(mo - nm);
                m[h] = nm;
            }
            inv[h] = 1.f / (sm[h] + 1e-16f);
        }

        for (int base = 0; base < deg; base += 32) {
            int k = base + lane;
            int src = 0;
            float al0 = 0.f, al1 = 0.f;
            if (k < deg) {
                src = col[start + k];
                if (H == 2) {
                    float2 sv = *reinterpret_cast<const float2*>(&s[src * 2]);
                    float e0 = sv.x + tn[0];
                    e0 = e0 > 0.f ? e0 : NEG_SLOPE * e0;
                    al0 = __expf(e0 - m[0]) * inv[0];
                    float e1 = sv.y + tn[1];
                    e1 = e1 > 0.f ? e1 : NEG_SLOPE * e1;
                    al1 = __expf(e1 - m[1]) * inv[1];
                } else {
                    float e = s[src] + tn[0];
                    e = e > 0.f ? e : NEG_SLOPE * e;
                    al0 = __expf(e - m[0]) * inv[0];
                }
            }
            gather(src, al0, al1, min(32, deg - base));
        }
    }

    if (H == 2) {
        float4 bv = *reinterpret_cast<const float4*>(bias + lane * 4);
        float4 v;
        v.x = acc.x + bv.x;
        v.y = acc.y + bv.y;
        v.z = acc.z + bv.z;
        v.w = acc.w + bv.w;
        if (RELU) {
            v.x = fmaxf(v.x, 0.f); v.y = fmaxf(v.y, 0.f);
            v.z = fmaxf(v.z, 0.f); v.w = fmaxf(v.w, 0.f);
        }
        *reinterpret_cast<float4*>(out + (size_t)node * 128 + lane * 4) = v;
    } else {
        float2 bv = *reinterpret_cast<const float2*>(bias + lane * 2);
        float2 v;
        v.x = acc.x + bv.x;
        v.y = acc.y + bv.y;
        if (RELU) {
            v.x = fmaxf(v.x, 0.f);
            v.y = fmaxf(v.y, 0.f);
        }
        *reinterpret_cast<float2*>(out + (size_t)node * 64 + lane * 2) = v;
    }
}

// ---------------- host launch ----------------
extern "C" void kernel_launch(void* const* d_in, const int* in_sizes, int n_in,
                              void* d_out, int out_size) {
    const float* x     = (const float*)d_in[0];
    const int*   ei    = (const int*)d_in[1];
    const float* W0    = (const float*)d_in[2];
    const float* as0   = (const float*)d_in[3];
    const float* ad0   = (const float*)d_in[4];
    const float* b0    = (const float*)d_in[5];
    const float* W1    = (const float*)d_in[6];
    const float* as1   = (const float*)d_in[7];
    const float* ad1   = (const float*)d_in[8];
    const float* b1    = (const float*)d_in[9];
    const float* W2    = (const float*)d_in[10];
    const float* as2   = (const float*)d_in[11];
    const float* ad2   = (const float*)d_in[12];
    const float* b2    = (const float*)d_in[13];
    const float* Wv    = (const float*)d_in[14];
    const float* bv    = (const float*)d_in[15];
    const float* Wt    = (const float*)d_in[16];
    const float* bt    = (const float*)d_in[17];

    int N = in_sizes[0] / 512;
    int E = in_sizes[1] / 2;

    float* out = (float*)d_out;
    float* h_out = out;
    float* vis = out + (size_t)N * 64;
    float* txt = out + (size_t)N * 64 * 2;

    float *h0, *h1, *sA, *tA, *Wcat, *bcat;
    int *deg, *rowptr, *cursor, *colA, *bsum, *bexc;
    cudaGetSymbolAddress((void**)&h0, g_h0);
    cudaGetSymbolAddress((void**)&h1, g_h1);
    cudaGetSymbolAddress((void**)&sA, g_s);
    cudaGetSymbolAddress((void**)&tA, g_t);
    cudaGetSymbolAddress((void**)&deg, g_deg);
    cudaGetSymbolAddress((void**)&rowptr, g_rowptr);
    cudaGetSymbolAddress((void**)&cursor, g_cursor);
    cudaGetSymbolAddress((void**)&colA, g_col);
    cudaGetSymbolAddress((void**)&bsum, g_bsum);
    cudaGetSymbolAddress((void**)&bexc, g_bexc);
    cudaGetSymbolAddress((void**)&Wcat, g_Wcat);
    cudaGetSymbolAddress((void**)&bcat, g_bcat);

    // dynamic smem: 3 stages of (A + B) at BK=32 + attention vectors
    const int SM128 = 3 * (128 * 32 + 32 * 128) * 4 + 2 * 128 * 4;  // 99328 B
    const int SM64  = 3 * (128 * 32 + 32 * 64) * 4 + 2 * 64 * 4;    // 74240 B
    cudaFuncSetAttribute(k_gemm<128>, cudaFuncAttributeMaxDynamicSharedMemorySize, SM128);
    cudaFuncSetAttribute(k_gemm<64>, cudaFuncAttributeMaxDynamicSharedMemorySize, SM64);

    static cudaStream_t s2 = nullptr;
    static cudaEvent_t evFork = nullptr, evJoin = nullptr;
    if (!s2) {
        cudaStreamCreateWithFlags(&s2, cudaStreamNonBlocking);
        cudaEventCreateWithFlags(&evFork, cudaEventDisableTiming);
        cudaEventCreateWithFlags(&evJoin, cudaEventDisableTiming);
    }

    int nb = (N + 255) / 256;
    int gblk = (N + 127) / 128;
    int wgrid = (N * 32 + 255) / 256;

    // ---- fork: 3 CSR kernels first, GEMM0 4th (ncu slot) ----
    cudaEventRecord(evFork, 0);
    cudaStreamWaitEvent(s2, evFork, 0);
    k_init_deg<<<nb, 256, 0, s2>>>(deg, N);
    k_hist<<<(E + 255) / 256, 256, 0, s2>>>(ei, E, deg);
    k_blocksums<<<nb, 256, 0, s2>>>(deg, bsum, N);

    k_gemm<128><<<gblk, 256, SM128>>>(x, W0, h0, nullptr, N, 512, nullptr, 0,
                                      as0, ad0, sA, tA);

    k_scan_top<<<1, 256, 0, s2>>>(bsum, bexc, nb);
    k_scan_apply<<<nb, 256, 0, s2>>>(deg, bexc, rowptr, cursor, colA, N);
    k_scatter<<<(E + 255) / 256, 256, 0, s2>>>(ei, E, cursor, colA);
    k_prep<<<(64 * 128 + 255) / 256, 256, 0, s2>>>(Wv, bv, Wt, bt, Wcat, bcat);
    cudaEventRecord(evJoin, s2);

    // ---- join ----
    cudaStreamWaitEvent(0, evJoin, 0);

    // ---- layer 0 aggregation ----
    k_aggw<2, true><<<wgrid, 256>>>(h0, sA, tA, rowptr, colA, b0, h1, N);

    // ---- layer 1 ----
    k_gemm<128><<<gblk, 256, SM128>>>(h1, W1, h0, nullptr, N, 128, nullptr, 0,
                                      as1, ad1, sA, tA);
    k_aggw<2, true><<<wgrid, 256>>>(h0, sA, tA, rowptr, colA, b1, h1, N);

    // ---- layer 2 (heads=1, no relu) ----
    k_gemm<64><<<gblk, 256, SM64>>>(h1, W2, h0, nullptr, N, 128, nullptr, 0,
                                    as2, ad2, sA, tA);
    k_aggw<1, false><<<wgrid, 256>>>(h0, sA, tA, rowptr, colA, b2, h_out, N);

    // ---- MLP heads: one combined GEMM with split store ----
    k_gemm<128><<<gblk, 256, SM128>>>(h_out, Wcat, vis, txt, N, 64, bcat, 1,
                                      nullptr, nullptr, nullptr, nullptr);
}